// round 13
// baseline (speedup 1.0000x reference)
#include <cuda_runtime.h>
#include <cuda_bf16.h>
#include <cstdint>

// Problem constants
#define BB   2
#define SS   2048
#define DD   1024
#define HH   16
#define HDIM 64
#define MROWS (BB*SS)      // 4096
typedef __nv_bfloat16 bf16;

// ---------------- scratch (no allocations allowed) ----------------
__device__ bf16 g_inqh[MROWS * DD], g_inql[MROWS * DD];
__device__ bf16 g_inkh[MROWS * DD], g_inkl[MROWS * DD];
__device__ bf16 g_wqh[DD * DD], g_wql[DD * DD];
__device__ bf16 g_wkh[DD * DD], g_wkl[DD * DD];
__device__ bf16 g_wvh[DD * DD], g_wvl[DD * DD];
__device__ bf16 g_woh[DD * DD], g_wol[DD * DD];
__device__ bf16 g_qh[MROWS * DD], g_ql[MROWS * DD];
__device__ bf16 g_kh[MROWS * DD], g_kl[MROWS * DD];
__device__ bf16 g_vh[MROWS * DD], g_vl[MROWS * DD];
__device__ bf16 g_ah[MROWS * DD], g_al[MROWS * DD];

// ============================================================================
// helpers
// ============================================================================
__device__ __forceinline__ uint32_t smem_u32(const void* p) {
    uint32_t a;
    asm("{ .reg .u64 t; cvta.to.shared.u64 t, %1; cvt.u32.u64 %0, t; }"
        : "=r"(a) : "l"(p));
    return a;
}
__device__ __forceinline__ void ldsm4(uint32_t* r, uint32_t addr) {
    asm volatile("ldmatrix.sync.aligned.m8n8.x4.shared.b16 {%0,%1,%2,%3}, [%4];"
                 : "=r"(r[0]), "=r"(r[1]), "=r"(r[2]), "=r"(r[3]) : "r"(addr));
}
__device__ __forceinline__ void ldsm4t(uint32_t* r, uint32_t addr) {
    asm volatile("ldmatrix.sync.aligned.m8n8.x4.trans.shared.b16 {%0,%1,%2,%3}, [%4];"
                 : "=r"(r[0]), "=r"(r[1]), "=r"(r[2]), "=r"(r[3]) : "r"(addr));
}
__device__ __forceinline__ void mma16816(float* c, const uint32_t* a,
                                         uint32_t b0, uint32_t b1) {
    asm volatile(
        "mma.sync.aligned.m16n8k16.row.col.f32.bf16.bf16.f32 "
        "{%0,%1,%2,%3}, {%4,%5,%6,%7}, {%8,%9}, {%0,%1,%2,%3};"
        : "+f"(c[0]), "+f"(c[1]), "+f"(c[2]), "+f"(c[3])
        : "r"(a[0]), "r"(a[1]), "r"(a[2]), "r"(a[3]), "r"(b0), "r"(b1));
}
__device__ __forceinline__ void splitpack(float x, float y, uint32_t& hi, uint32_t& lo) {
    bf16 hx = __float2bfloat16(x), hy = __float2bfloat16(y);
    float rx = x - __bfloat162float(hx);
    float ry = y - __bfloat162float(hy);
    bf16 lx = __float2bfloat16(rx), ly = __float2bfloat16(ry);
    hi = (uint32_t)__bfloat16_as_ushort(hx) | ((uint32_t)__bfloat16_as_ushort(hy) << 16);
    lo = (uint32_t)__bfloat16_as_ushort(lx) | ((uint32_t)__bfloat16_as_ushort(ly) << 16);
}

#define CP_ASYNC16(dst, src) \
    asm volatile("cp.async.cg.shared.global [%0], [%1], 16;" \
                 :: "r"(dst), "l"(src) : "memory")
#define CP_COMMIT() asm volatile("cp.async.commit_group;" ::: "memory")
#define CP_WAIT0()  asm volatile("cp.async.wait_group 0;" ::: "memory")
#define CP_WAIT1()  asm volatile("cp.async.wait_group 1;" ::: "memory")
#define CP_WAIT2()  asm volatile("cp.async.wait_group 2;" ::: "memory")

// ============================================================================
// split kernels (identical to passing R9)
// ============================================================================
__global__ void split_fused_kernel(const float* __restrict__ s0, bf16* h0, bf16* l0,
                                   const float* __restrict__ s1, bf16* h1, bf16* l1)
{
    const float* src = blockIdx.z ? s1 : s0;
    bf16* hi = blockIdx.z ? h1 : h0;
    bf16* lo = blockIdx.z ? l1 : l0;
    const int i = (blockIdx.x * 256 + threadIdx.x) * 4;
    float4 v = *(const float4*)(src + i);
    uint32_t a0, b0, a1, b1;
    splitpack(v.x, v.y, a0, b0);
    splitpack(v.z, v.w, a1, b1);
    *(uint2*)(hi + i) = make_uint2(a0, a1);
    *(uint2*)(lo + i) = make_uint2(b0, b1);
}

__global__ void splitw_fused_kernel(
    const float* __restrict__ W0, bf16* th0, bf16* tl0,
    const float* __restrict__ W1, bf16* th1, bf16* tl1,
    const float* __restrict__ W2, bf16* th2, bf16* tl2,
    const float* __restrict__ W3, bf16* th3, bf16* tl3)
{
    const float* W; bf16* th; bf16* tl;
    switch (blockIdx.z) {
        case 0: W = W0; th = th0; tl = tl0; break;
        case 1: W = W1; th = th1; tl = tl1; break;
        case 2: W = W2; th = th2; tl = tl2; break;
        default: W = W3; th = th3; tl = tl3; break;
    }
    __shared__ float t[32][33];
    const int tx = threadIdx.x, ty = threadIdx.y;
    const int k0 = blockIdx.y * 32, n0 = blockIdx.x * 32;
    #pragma unroll
    for (int i = 0; i < 4; i++)
        t[ty + i * 8][tx] = W[(size_t)(k0 + ty + i * 8) * DD + n0 + tx];
    __syncthreads();
    #pragma unroll
    for (int i = 0; i < 4; i++) {
        const float v = t[tx][ty + i * 8];
        bf16 h = __float2bfloat16(v);
        bf16 l = __float2bfloat16(v - __bfloat162float(h));
        const size_t o = (size_t)(n0 + ty + i * 8) * DD + k0 + tx;
        th[o] = h; tl[o] = l;
    }
}

// ============================================================================
// GEMM v4: CTA tile 64(m) x 128(n), 8 warps (warp tile 32x32), 3-pass bf16.
// 3-stage cp.async with FLASH-STYLE sync (the formally correct ordering):
//   prefetch(kc+2) -> commit -> wait_group 2 -> __syncthreads (publish)
//   -> compute(stage kc) -> __syncthreads (WAR-protect next prefetch target)
// stage layout: AHI 4K | ALO 4K | BHI 8K | BLO 8K = 24K
// ============================================================================
#define GSTG 24576
#define GEMM_SMEM (3 * GSTG)   // 73728 -> 3 CTAs/SM = 216K

template<bool F32OUT>
__device__ __forceinline__ void gemm_body(
    const bf16* __restrict__ Ah, const bf16* __restrict__ Al,
    const bf16* __restrict__ Bh, const bf16* __restrict__ Bl,
    const float* __restrict__ bias, float scale,
    bf16* __restrict__ Ch, bf16* __restrict__ Cl, float* __restrict__ Cf,
    int bm, int bn)
{
    extern __shared__ char smem[];
    const uint32_t sb = smem_u32(smem);
    const int tid = threadIdx.x, wid = tid >> 5, lane = tid & 31;
    const int mw = wid >> 2;        // 0..1 (m half, 32 rows)
    const int nwq = wid & 3;        // 0..3 (n quarter, 32 cols)

    // A loader: 64 rows x 64B, one 16B chunk per thread
    const int lrA = tid >> 2, lcA = tid & 3;
    const bf16* rAh = Ah + (size_t)(bm * 64 + lrA) * DD;
    const bf16* rAl = Al + (size_t)(bm * 64 + lrA) * DD;
    const uint32_t ldstA = (uint32_t)(lrA * 64 + (lcA ^ ((lrA >> 1) & 3)) * 16);
    // B loader: 128 rows x 64B, two chunks per thread
    const int lrB = tid >> 1, lc0B = (tid & 1) * 2;
    const bf16* rBh = Bh + (size_t)(bn * 128 + lrB) * DD;
    const bf16* rBl = Bl + (size_t)(bn * 128 + lrB) * DD;
    const uint32_t xlB = (lrB >> 1) & 3;
    uint32_t ldstB[2];
    #pragma unroll
    for (int j = 0; j < 2; j++)
        ldstB[j] = (uint32_t)(lrB * 64 + ((lc0B + j) ^ xlB) * 16);

    // ldsm addressing (tile-row offsets are multiples of 16 -> xg from lrow ok)
    const int lrow = lane & 15, cl = lane >> 4;
    const uint32_t xg = (lrow >> 1) & 3;
    uint32_t offA[2][2], offB[2][2];
    #pragma unroll
    for (int ks = 0; ks < 2; ks++) {
        const uint32_t cc = (uint32_t)(((ks * 2 + cl) ^ xg) * 16);
        #pragma unroll
        for (int mi = 0; mi < 2; mi++)
            offA[mi][ks] = (uint32_t)((mw * 32 + mi * 16 + lrow) * 64) + cc;
        #pragma unroll
        for (int np = 0; np < 2; np++)
            offB[np][ks] = (uint32_t)((nwq * 32 + np * 16 + lrow) * 64) + cc;
    }

    float acc[2][4][4];   // [mi][np*2+hf][quad]
    #pragma unroll
    for (int i = 0; i < 2; i++)
        #pragma unroll
        for (int j = 0; j < 4; j++)
            #pragma unroll
            for (int q = 0; q < 4; q++) acc[i][j][q] = 0.f;

    // prologue: chunks 0,1 -> stages 0,1
    #pragma unroll
    for (int st = 0; st < 2; st++) {
        const uint32_t base = sb + st * GSTG;
        const int ke = st * 32;
        CP_ASYNC16(base + ldstA,        rAh + ke + lcA * 8);
        CP_ASYNC16(base + 4096 + ldstA, rAl + ke + lcA * 8);
        #pragma unroll
        for (int j = 0; j < 2; j++) {
            const int eo = ke + (lc0B + j) * 8;
            CP_ASYNC16(base + 8192 + ldstB[j],  rBh + eo);
            CP_ASYNC16(base + 16384 + ldstB[j], rBl + eo);
        }
        CP_COMMIT();
    }

    int stage = 0;
    for (int kc = 0; kc < 32; kc++) {
        // prefetch chunk kc+2 into stage (kc+2)%3 == (kc-1)%3.
        // WAR-safe: readers of that stage finished before end-of-(kc-1) barrier.
        if (kc + 2 < 32) {
            const uint32_t base = sb + ((stage + 2) % 3) * GSTG;
            const int ke = (kc + 2) * 32;
            CP_ASYNC16(base + ldstA,        rAh + ke + lcA * 8);
            CP_ASYNC16(base + 4096 + ldstA, rAl + ke + lcA * 8);
            #pragma unroll
            for (int j = 0; j < 2; j++) {
                const int eo = ke + (lc0B + j) * 8;
                CP_ASYNC16(base + 8192 + ldstB[j],  rBh + eo);
                CP_ASYNC16(base + 16384 + ldstB[j], rBl + eo);
            }
            CP_COMMIT();
            CP_WAIT2();      // retire own group for chunk kc
        } else if (kc + 1 < 32) {
            CP_WAIT1();
        } else {
            CP_WAIT0();
        }
        __syncthreads();     // PUBLISH chunk kc to all threads (the R12 fix)

        const uint32_t B0 = sb + stage * GSTG;
        #pragma unroll
        for (int ks = 0; ks < 2; ks++) {
            uint32_t ah[2][4], al[2][4], bh[2][4], bl[2][4];
            ldsm4(ah[0], B0 + offA[0][ks]);
            ldsm4(ah[1], B0 + offA[1][ks]);
            ldsm4(al[0], B0 + 4096 + offA[0][ks]);
            ldsm4(al[1], B0 + 4096 + offA[1][ks]);
            ldsm4(bh[0], B0 + 8192 + offB[0][ks]);
            ldsm4(bh[1], B0 + 8192 + offB[1][ks]);
            ldsm4(bl[0], B0 + 16384 + offB[0][ks]);
            ldsm4(bl[1], B0 + 16384 + offB[1][ks]);
            // pass-major: 8 independent accumulators per pass
            #pragma unroll
            for (int np = 0; np < 2; np++)
                #pragma unroll
                for (int hf = 0; hf < 2; hf++)
                    #pragma unroll
                    for (int mi = 0; mi < 2; mi++)
                        mma16816(acc[mi][np * 2 + hf], ah[mi],
                                 bh[np][hf], bh[np][hf + 2]);
            #pragma unroll
            for (int np = 0; np < 2; np++)
                #pragma unroll
                for (int hf = 0; hf < 2; hf++)
                    #pragma unroll
                    for (int mi = 0; mi < 2; mi++)
                        mma16816(acc[mi][np * 2 + hf], ah[mi],
                                 bl[np][hf], bl[np][hf + 2]);
            #pragma unroll
            for (int np = 0; np < 2; np++)
                #pragma unroll
                for (int hf = 0; hf < 2; hf++)
                    #pragma unroll
                    for (int mi = 0; mi < 2; mi++)
                        mma16816(acc[mi][np * 2 + hf], al[mi],
                                 bh[np][hf], bh[np][hf + 2]);
        }
        __syncthreads();     // WAR: protect stage kc%3 before iter kc+1 prefetch
        stage = (stage + 1) % 3;
    }

    const int tg = lane >> 2, tq = lane & 3;
    #pragma unroll
    for (int mi = 0; mi < 2; mi++) {
        const int gr = bm * 64 + mw * 32 + mi * 16 + tg;
        #pragma unroll
        for (int nj = 0; nj < 4; nj++) {
            const int gc = bn * 128 + nwq * 32 + nj * 8 + tq * 2;
            const float b0 = bias[gc], b1 = bias[gc + 1];
            float* c = acc[mi][nj];
            const float v0 = (c[0] + b0) * scale, v1 = (c[1] + b1) * scale;
            const float v2 = (c[2] + b0) * scale, v3 = (c[3] + b1) * scale;
            if (F32OUT) {
                *(float2*)(Cf + (size_t)gr * DD + gc)       = make_float2(v0, v1);
                *(float2*)(Cf + (size_t)(gr + 8) * DD + gc) = make_float2(v2, v3);
            } else {
                uint32_t h, l;
                splitpack(v0, v1, h, l);
                *(uint32_t*)(Ch + (size_t)gr * DD + gc) = h;
                *(uint32_t*)(Cl + (size_t)gr * DD + gc) = l;
                splitpack(v2, v3, h, l);
                *(uint32_t*)(Ch + (size_t)(gr + 8) * DD + gc) = h;
                *(uint32_t*)(Cl + (size_t)(gr + 8) * DD + gc) = l;
            }
        }
    }
}

template<bool F32OUT>
__global__ __launch_bounds__(256, 3)
void gemm_bf16_kernel(const bf16* __restrict__ Ah, const bf16* __restrict__ Al,
                      const bf16* __restrict__ Bh, const bf16* __restrict__ Bl,
                      const float* __restrict__ bias, float scale,
                      bf16* __restrict__ Ch, bf16* __restrict__ Cl,
                      float* __restrict__ Cf)
{
    gemm_body<F32OUT>(Ah, Al, Bh, Bl, bias, scale, Ch, Cl, Cf,
                      blockIdx.y, blockIdx.x);
}

// fused Q/K projection: z=0 -> Q (scaled), z=1 -> K
__global__ __launch_bounds__(256, 3)
void qk_gemm_kernel(
    const bf16* iqh, const bf16* iql, const bf16* ikh, const bf16* ikl,
    const bf16* wqh, const bf16* wql, const bf16* wkh, const bf16* wkl,
    const float* bq, const float* bk,
    bf16* qh, bf16* ql, bf16* kh, bf16* kl)
{
    if (blockIdx.z == 0)
        gemm_body<false>(iqh, iql, wqh, wql, bq, 0.125f, qh, ql, nullptr,
                         blockIdx.y, blockIdx.x);
    else
        gemm_body<false>(ikh, ikl, wkh, wkl, bk, 1.0f, kh, kl, nullptr,
                         blockIdx.y, blockIdx.x);
}

// ============================================================================
// flash attention (identical to passing R9): pre-split bf16, SW128, 2-stage KV.
// ============================================================================
#define FKV0 32768
#define FKVSTG 32768
#define FLASH_SMEM 98304

__global__ __launch_bounds__(256, 2)
void flash_kernel(const bf16* __restrict__ Qh, const bf16* __restrict__ Ql,
                  const bf16* __restrict__ Kh, const bf16* __restrict__ Kl,
                  const bf16* __restrict__ Vh, const bf16* __restrict__ Vl,
                  bf16* __restrict__ Oh, bf16* __restrict__ Ol)
{
    extern __shared__ char smem[];
    const uint32_t sb = smem_u32(smem);
    const int tid = threadIdx.x, wid = tid >> 5, lane = tid & 31;
    const int qt = (gridDim.x - 1) - blockIdx.x;
    const int h = blockIdx.y, b = blockIdx.z;
    const size_t hbase = ((size_t)b * SS) * DD + h * HDIM;
    const int nkt = 2 * qt + 2;

    const int qlr = tid >> 1, qc0 = (tid & 1) * 4;
    const int klr = tid >> 2, kc0 = (tid & 3) * 2;
    const bf16* rQh = Qh + hbase + (size_t)(qt * 128 + qlr) * DD;
    const bf16* rQl = Ql + hbase + (size_t)(qt * 128 + qlr) * DD;
    const bf16* rKh = Kh + hbase + (size_t)klr * DD;
    const bf16* rKl = Kl + hbase + (size_t)klr * DD;
    const bf16* rVh = Vh + hbase + (size_t)klr * DD;
    const bf16* rVl = Vl + hbase + (size_t)klr * DD;
    const uint32_t qx = qlr & 7, kx = klr & 7;

    #pragma unroll
    for (int j = 0; j < 4; j++) {
        const uint32_t d = (uint32_t)(qlr * 128 + ((qc0 + j) ^ qx) * 16);
        const int eo = (qc0 + j) * 8;
        CP_ASYNC16(sb + d,         rQh + eo);
        CP_ASYNC16(sb + 16384 + d, rQl + eo);
    }
    #pragma unroll
    for (int j = 0; j < 2; j++) {
        const uint32_t d = (uint32_t)(klr * 128 + ((kc0 + j) ^ kx) * 16);
        const int eo = (kc0 + j) * 8;
        CP_ASYNC16(sb + FKV0 + d,         rKh + eo);
        CP_ASYNC16(sb + FKV0 + 8192 + d,  rKl + eo);
        CP_ASYNC16(sb + FKV0 + 16384 + d, rVh + eo);
        CP_ASYNC16(sb + FKV0 + 24576 + d, rVl + eo);
    }
    CP_COMMIT();

    const int lrow = lane & 15, cl = lane >> 4;
    const uint32_t x = lrow & 7;
    const uint32_t rb = (uint32_t)(lrow * 128);
    const uint32_t qwb = (uint32_t)(wid * 2048);

    float oacc[8][4];
    #pragma unroll
    for (int t = 0; t < 8; t++)
        #pragma unroll
        for (int j = 0; j < 4; j++) oacc[t][j] = 0.f;
    float m0 = -1e30f, m1 = -1e30f, l0 = 0.f, l1 = 0.f;

    for (int kt = 0; kt < nkt; kt++) {
        if (kt + 1 < nkt) {
            const uint32_t base = sb + FKV0 + ((kt + 1) & 1) * FKVSTG;
            const size_t ro = (size_t)(kt + 1) * 64 * DD;
            #pragma unroll
            for (int j = 0; j < 2; j++) {
                const uint32_t d = (uint32_t)(klr * 128 + ((kc0 + j) ^ kx) * 16);
                const int eo = (kc0 + j) * 8;
                CP_ASYNC16(base + d,         rKh + ro + eo);
                CP_ASYNC16(base + 8192 + d,  rKl + ro + eo);
                CP_ASYNC16(base + 16384 + d, rVh + ro + eo);
                CP_ASYNC16(base + 24576 + d, rVl + ro + eo);
            }
            CP_COMMIT();
            CP_WAIT1();
        } else {
            CP_WAIT0();
        }
        __syncthreads();

        const uint32_t kvb = sb + FKV0 + (kt & 1) * FKVSTG;

        float s[8][4];
        #pragma unroll
        for (int t = 0; t < 8; t++)
            #pragma unroll
            for (int j = 0; j < 4; j++) s[t][j] = 0.f;

        #pragma unroll
        for (int ks = 0; ks < 4; ks++) {
            const uint32_t cc = ((uint32_t)(ks * 2 + cl) ^ x) * 16;
            uint32_t qhi[4], qlo[4];
            ldsm4(qhi, sb + qwb + rb + cc);
            ldsm4(qlo, sb + 16384 + qwb + rb + cc);
            #pragma unroll
            for (int np = 0; np < 4; np++) {
                uint32_t khi[4], klo[4];
                const uint32_t ko = kvb + (uint32_t)(np * 2048) + rb + cc;
                ldsm4(khi, ko);
                ldsm4(klo, ko + 8192);
                float* s0 = s[np * 2 + 0];
                float* s1 = s[np * 2 + 1];
                mma16816(s0, qhi, khi[0], khi[2]);
                mma16816(s1, qhi, khi[1], khi[3]);
                mma16816(s0, qhi, klo[0], klo[2]);
                mma16816(s1, qhi, klo[1], klo[3]);
                mma16816(s0, qlo, khi[0], khi[2]);
                mma16816(s1, qlo, khi[1], khi[3]);
            }
        }

        if (kt >= 2 * qt) {
            const int off = (kt - 2 * qt) * 64;
            const int r0 = wid * 16 + (lane >> 2);
            const int cb = (lane & 3) * 2;
            #pragma unroll
            for (int t = 0; t < 8; t++)
                #pragma unroll
                for (int j = 0; j < 2; j++) {
                    const int cg = off + t * 8 + cb + j;
                    if (cg > r0)     s[t][j]     = -1e30f;
                    if (cg > r0 + 8) s[t][2 + j] = -1e30f;
                }
        }

        float mx0 = -1e30f, mx1 = -1e30f;
        #pragma unroll
        for (int t = 0; t < 8; t++) {
            mx0 = fmaxf(mx0, fmaxf(s[t][0], s[t][1]));
            mx1 = fmaxf(mx1, fmaxf(s[t][2], s[t][3]));
        }
        mx0 = fmaxf(mx0, __shfl_xor_sync(0xffffffffu, mx0, 1));
        mx0 = fmaxf(mx0, __shfl_xor_sync(0xffffffffu, mx0, 2));
        mx1 = fmaxf(mx1, __shfl_xor_sync(0xffffffffu, mx1, 1));
        mx1 = fmaxf(mx1, __shfl_xor_sync(0xffffffffu, mx1, 2));

        const float mn0 = fmaxf(m0, mx0);
        const float mn1 = fmaxf(m1, mx1);
        const float al0 = __expf(m0 - mn0);
        const float al1 = __expf(m1 - mn1);
        m0 = mn0; m1 = mn1;

        float ls0 = 0.f, ls1 = 0.f;
        #pragma unroll
        for (int t = 0; t < 8; t++) {
            s[t][0] = __expf(s[t][0] - mn0); ls0 += s[t][0];
            s[t][1] = __expf(s[t][1] - mn0); ls0 += s[t][1];
            s[t][2] = __expf(s[t][2] - mn1); ls1 += s[t][2];
            s[t][3] = __expf(s[t][3] - mn1); ls1 += s[t][3];
        }
        ls0 += __shfl_xor_sync(0xffffffffu, ls0, 1);
        ls0 += __shfl_xor_sync(0xffffffffu, ls0, 2);
        ls1 += __shfl_xor_sync(0xffffffffu, ls1, 1);
        ls1 += __shfl_xor_sync(0xffffffffu, ls1, 2);
        l0 = l0 * al0 + ls0;
        l1 = l1 * al1 + ls1;
        #pragma unroll
        for (int t = 0; t < 8; t++) {
            oacc[t][0] *= al0; oacc[t][1] *= al0;
            oacc[t][2] *= al1; oacc[t][3] *= al1;
        }

        #pragma unroll
        for (int t = 0; t < 4; t++) {
            uint32_t aPhi[4], aPlo[4];
            splitpack(s[2 * t][0],     s[2 * t][1],     aPhi[0], aPlo[0]);
            splitpack(s[2 * t][2],     s[2 * t][3],     aPhi[1], aPlo[1]);
            splitpack(s[2 * t + 1][0], s[2 * t + 1][1], aPhi[2], aPlo[2]);
            splitpack(s[2 * t + 1][2], s[2 * t + 1][3], aPhi[3], aPlo[3]);
            #pragma unroll
            for (int np = 0; np < 4; np++) {
                const uint32_t cc = ((uint32_t)(np * 2 + cl) ^ x) * 16;
                const uint32_t vo = kvb + 16384 + (uint32_t)(t * 2048) + rb + cc;
                uint32_t vhi[4], vlo[4];
                ldsm4t(vhi, vo);
                ldsm4t(vlo, vo + 8192);
                float* o0 = oacc[np * 2 + 0];
                float* o1 = oacc[np * 2 + 1];
                mma16816(o0, aPhi, vhi[0], vhi[1]);
                mma16816(o1, aPhi, vhi[2], vhi[3]);
                mma16816(o0, aPhi, vlo[0], vlo[1]);
                mma16816(o1, aPhi, vlo[2], vlo[3]);
                mma16816(o0, aPlo, vhi[0], vhi[1]);
                mma16816(o1, aPlo, vhi[2], vhi[3]);
            }
        }
        __syncthreads();
    }

    const float inv0 = 1.0f / l0;
    const float inv1 = 1.0f / l1;
    const int r0 = qt * 128 + wid * 16 + (lane >> 2);
    const int cb = (lane & 3) * 2;
    #pragma unroll
    for (int t = 0; t < 8; t++) {
        uint32_t h0, lo0, h1, lo1;
        splitpack(oacc[t][0] * inv0, oacc[t][1] * inv0, h0, lo0);
        splitpack(oacc[t][2] * inv1, oacc[t][3] * inv1, h1, lo1);
        const size_t o0 = hbase + (size_t)r0 * DD + t * 8 + cb;
        const size_t o1 = hbase + (size_t)(r0 + 8) * DD + t * 8 + cb;
        *(uint32_t*)(Oh + o0) = h0;
        *(uint32_t*)(Ol + o0) = lo0;
        *(uint32_t*)(Oh + o1) = h1;
        *(uint32_t*)(Ol + o1) = lo1;
    }
}

// ---------------- launch ----------------
extern "C" void kernel_launch(void* const* d_in, const int* in_sizes, int n_in,
                              void* d_out, int out_size)
{
    const float* queries = (const float*)d_in[0];
    const float* keys    = (const float*)d_in[1];
    const float* Wq = (const float*)d_in[4];
    const float* bq = (const float*)d_in[5];
    const float* Wk = (const float*)d_in[6];
    const float* bk = (const float*)d_in[7];
    const float* Wv = (const float*)d_in[8];
    const float* bv = (const float*)d_in[9];
    const float* Wo = (const float*)d_in[10];
    const float* bo = (const float*)d_in[11];
    float* out = (float*)d_out;

    bf16 *inqh, *inql, *inkh, *inkl;
    bf16 *wqh, *wql, *wkh, *wkl, *wvh, *wvl, *woh, *wol;
    bf16 *qh, *ql, *kh, *kl, *vh, *vl, *ah, *al;
    cudaGetSymbolAddress((void**)&inqh, g_inqh); cudaGetSymbolAddress((void**)&inql, g_inql);
    cudaGetSymbolAddress((void**)&inkh, g_inkh); cudaGetSymbolAddress((void**)&inkl, g_inkl);
    cudaGetSymbolAddress((void**)&wqh, g_wqh); cudaGetSymbolAddress((void**)&wql, g_wql);
    cudaGetSymbolAddress((void**)&wkh, g_wkh); cudaGetSymbolAddress((void**)&wkl, g_wkl);
    cudaGetSymbolAddress((void**)&wvh, g_wvh); cudaGetSymbolAddress((void**)&wvl, g_wvl);
    cudaGetSymbolAddress((void**)&woh, g_woh); cudaGetSymbolAddress((void**)&wol, g_wol);
    cudaGetSymbolAddress((void**)&qh, g_qh); cudaGetSymbolAddress((void**)&ql, g_ql);
    cudaGetSymbolAddress((void**)&kh, g_kh); cudaGetSymbolAddress((void**)&kl, g_kl);
    cudaGetSymbolAddress((void**)&vh, g_vh); cudaGetSymbolAddress((void**)&vl, g_vl);
    cudaGetSymbolAddress((void**)&ah, g_ah); cudaGetSymbolAddress((void**)&al, g_al);

    cudaFuncSetAttribute(gemm_bf16_kernel<false>,
                         cudaFuncAttributeMaxDynamicSharedMemorySize, GEMM_SMEM);
    cudaFuncSetAttribute(gemm_bf16_kernel<true>,
                         cudaFuncAttributeMaxDynamicSharedMemorySize, GEMM_SMEM);
    cudaFuncSetAttribute(qk_gemm_kernel,
                         cudaFuncAttributeMaxDynamicSharedMemorySize, GEMM_SMEM);
    cudaFuncSetAttribute(flash_kernel,
                         cudaFuncAttributeMaxDynamicSharedMemorySize, FLASH_SMEM);

    // 1) splits (launches 1-2)
    const int selem = MROWS * DD;
    dim3 sgrid(selem / 1024, 1, 2);
    split_fused_kernel<<<sgrid, 256>>>(queries, inqh, inql, keys, inkh, inkl);
    dim3 wtb(32, 8), wtg(32, 32, 4);
    splitw_fused_kernel<<<wtg, wtb>>>(Wq, wqh, wql, Wk, wkh, wkl,
                                      Wv, wvh, wvl, Wo, woh, wol);

    // 2) fused Q+K projections (launch 3; 1024 CTAs of 64x128)
    dim3 gblk(256);
    dim3 qkgrid(DD / 128, MROWS / 64, 2);
    qk_gemm_kernel<<<qkgrid, gblk, GEMM_SMEM>>>(
        inqh, inql, inkh, inkl,
        wqh, wql, wkh, wkl, bq, bk,
        qh, ql, kh, kl);

    // 3) V projection from projected K (launch 4; 512 CTAs)
    dim3 ggrid(DD / 128, MROWS / 64);
    gemm_bf16_kernel<false><<<ggrid, gblk, GEMM_SMEM>>>(
        kh, kl, wvh, wvl, bv, 1.0f, vh, vl, nullptr);

    // 4) attention (launch 5)
    dim3 fgrid(SS / 128, HH, BB);
    flash_kernel<<<fgrid, dim3(256), FLASH_SMEM>>>(qh, ql, kh, kl, vh, vl, ah, al);

    // 5) output projection (launch 6 -> profiled by ncu -s 5 -c 1)
    gemm_bf16_kernel<true><<<ggrid, gblk, GEMM_SMEM>>>(
        ah, al, woh, wol, bo, 1.0f, nullptr, nullptr, out);
}

// round 14
// speedup vs baseline: 1.2626x; 1.2626x over previous
#include <cuda_runtime.h>
#include <cuda_fp16.h>
#include <cstdint>

// Problem constants
#define BB   2
#define SS   2048
#define DD   1024
#define HH   16
#define HDIM 64
#define MROWS (BB*SS)      // 4096
typedef __half fp16;

// ---------------- scratch (no allocations allowed) ----------------
__device__ fp16 g_inqh[MROWS * DD], g_inql[MROWS * DD];
__device__ fp16 g_inkh[MROWS * DD], g_inkl[MROWS * DD];
__device__ fp16 g_wq16[DD * DD];   // W^T [n][k] single fp16
__device__ fp16 g_wk16[DD * DD];
__device__ fp16 g_wv16[DD * DD];
__device__ fp16 g_wo16[DD * DD];
__device__ fp16 g_qh[MROWS * DD], g_ql[MROWS * DD];
__device__ fp16 g_kh[MROWS * DD], g_kl[MROWS * DD];
__device__ fp16 g_vh[MROWS * DD], g_vl[MROWS * DD];
__device__ fp16 g_ah[MROWS * DD], g_al[MROWS * DD];

// ============================================================================
// helpers
// ============================================================================
__device__ __forceinline__ uint32_t smem_u32(const void* p) {
    uint32_t a;
    asm("{ .reg .u64 t; cvta.to.shared.u64 t, %1; cvt.u32.u64 %0, t; }"
        : "=r"(a) : "l"(p));
    return a;
}
__device__ __forceinline__ void ldsm4(uint32_t* r, uint32_t addr) {
    asm volatile("ldmatrix.sync.aligned.m8n8.x4.shared.b16 {%0,%1,%2,%3}, [%4];"
                 : "=r"(r[0]), "=r"(r[1]), "=r"(r[2]), "=r"(r[3]) : "r"(addr));
}
__device__ __forceinline__ void ldsm4t(uint32_t* r, uint32_t addr) {
    asm volatile("ldmatrix.sync.aligned.m8n8.x4.trans.shared.b16 {%0,%1,%2,%3}, [%4];"
                 : "=r"(r[0]), "=r"(r[1]), "=r"(r[2]), "=r"(r[3]) : "r"(addr));
}
// fp16 mma with fp32 accumulate
__device__ __forceinline__ void mma16816(float* c, const uint32_t* a,
                                         uint32_t b0, uint32_t b1) {
    asm volatile(
        "mma.sync.aligned.m16n8k16.row.col.f32.f16.f16.f32 "
        "{%0,%1,%2,%3}, {%4,%5,%6,%7}, {%8,%9}, {%0,%1,%2,%3};"
        : "+f"(c[0]), "+f"(c[1]), "+f"(c[2]), "+f"(c[3])
        : "r"(a[0]), "r"(a[1]), "r"(a[2]), "r"(a[3]), "r"(b0), "r"(b1));
}
__device__ __forceinline__ void splitpack(float x, float y, uint32_t& hi, uint32_t& lo) {
    fp16 hx = __float2half_rn(x), hy = __float2half_rn(y);
    float rx = x - __half2float(hx);
    float ry = y - __half2float(hy);
    fp16 lx = __float2half_rn(rx), ly = __float2half_rn(ry);
    hi = (uint32_t)__half_as_ushort(hx) | ((uint32_t)__half_as_ushort(hy) << 16);
    lo = (uint32_t)__half_as_ushort(lx) | ((uint32_t)__half_as_ushort(ly) << 16);
}

#define CP_ASYNC16(dst, src) \
    asm volatile("cp.async.cg.shared.global [%0], [%1], 16;" \
                 :: "r"(dst), "l"(src) : "memory")
#define CP_COMMIT() asm volatile("cp.async.commit_group;" ::: "memory")
#define CP_WAIT0()  asm volatile("cp.async.wait_group 0;" ::: "memory")
#define CP_WAIT1()  asm volatile("cp.async.wait_group 1;" ::: "memory")
#define CP_WAIT2()  asm volatile("cp.async.wait_group 2;" ::: "memory")

// ============================================================================
// split kernels
// ============================================================================
__global__ void split_fused_kernel(const float* __restrict__ s0, fp16* h0, fp16* l0,
                                   const float* __restrict__ s1, fp16* h1, fp16* l1)
{
    const float* src = blockIdx.z ? s1 : s0;
    fp16* hi = blockIdx.z ? h1 : h0;
    fp16* lo = blockIdx.z ? l1 : l0;
    const int i = (blockIdx.x * 256 + threadIdx.x) * 4;
    float4 v = *(const float4*)(src + i);
    uint32_t a0, b0, a1, b1;
    splitpack(v.x, v.y, a0, b0);
    splitpack(v.z, v.w, a1, b1);
    *(uint2*)(hi + i) = make_uint2(a0, a1);
    *(uint2*)(lo + i) = make_uint2(b0, b1);
}

// W [k][n] fp32 -> Wt [n][k] single fp16, smem tile transpose; z selects matrix
__global__ void splitw_fused_kernel(
    const float* __restrict__ W0, fp16* t0,
    const float* __restrict__ W1, fp16* t1,
    const float* __restrict__ W2, fp16* t2,
    const float* __restrict__ W3, fp16* t3)
{
    const float* W; fp16* th;
    switch (blockIdx.z) {
        case 0: W = W0; th = t0; break;
        case 1: W = W1; th = t1; break;
        case 2: W = W2; th = t2; break;
        default: W = W3; th = t3; break;
    }
    __shared__ float t[32][33];
    const int tx = threadIdx.x, ty = threadIdx.y;
    const int k0 = blockIdx.y * 32, n0 = blockIdx.x * 32;
    #pragma unroll
    for (int i = 0; i < 4; i++)
        t[ty + i * 8][tx] = W[(size_t)(k0 + ty + i * 8) * DD + n0 + tx];
    __syncthreads();
    #pragma unroll
    for (int i = 0; i < 4; i++)
        th[(size_t)(n0 + ty + i * 8) * DD + k0 + tx] =
            __float2half_rn(t[tx][ty + i * 8]);
}

// ============================================================================
// GEMM: CTA tile 64(m) x 128(n), 8 warps (warp tile 32x32).
// A fp16 hi/lo (2 passes, exact), B single fp16. 3-stage cp.async with the
// R13-PROVEN sync: prefetch -> commit -> wait -> __syncthreads (publish)
// -> compute -> __syncthreads (WAR).  stage: AHI 4K | ALO 4K | B 8K = 16K
// ============================================================================
#define GSTG 16384
#define GEMM_SMEM (3 * GSTG)   // 49152 -> 3 CTAs/SM

template<bool F32OUT>
__device__ __forceinline__ void gemm_body(
    const fp16* __restrict__ Ah, const fp16* __restrict__ Al,
    const fp16* __restrict__ B,
    const float* __restrict__ bias, float scale,
    fp16* __restrict__ Ch, fp16* __restrict__ Cl, float* __restrict__ Cf,
    int bm, int bn)
{
    extern __shared__ char smem[];
    const uint32_t sb = smem_u32(smem);
    const int tid = threadIdx.x, wid = tid >> 5, lane = tid & 31;
    const int mw = wid >> 2;        // 0..1 (m half, 32 rows)
    const int nwq = wid & 3;        // 0..3 (n quarter, 32 cols)

    // A loader: 64 rows x 64B, one 16B chunk per thread
    const int lrA = tid >> 2, lcA = tid & 3;
    const fp16* rAh = Ah + (size_t)(bm * 64 + lrA) * DD;
    const fp16* rAl = Al + (size_t)(bm * 64 + lrA) * DD;
    const uint32_t ldstA = (uint32_t)(lrA * 64 + (lcA ^ ((lrA >> 1) & 3)) * 16);
    // B loader: 128 rows x 64B, two chunks per thread
    const int lrB = tid >> 1, lc0B = (tid & 1) * 2;
    const fp16* rB = B + (size_t)(bn * 128 + lrB) * DD;
    const uint32_t xlB = (lrB >> 1) & 3;
    uint32_t ldstB[2];
    #pragma unroll
    for (int j = 0; j < 2; j++)
        ldstB[j] = (uint32_t)(lrB * 64 + ((lc0B + j) ^ xlB) * 16);

    const int lrow = lane & 15, cl = lane >> 4;
    const uint32_t xg = (lrow >> 1) & 3;
    uint32_t offA[2][2], offB[2][2];
    #pragma unroll
    for (int ks = 0; ks < 2; ks++) {
        const uint32_t cc = (uint32_t)(((ks * 2 + cl) ^ xg) * 16);
        #pragma unroll
        for (int mi = 0; mi < 2; mi++)
            offA[mi][ks] = (uint32_t)((mw * 32 + mi * 16 + lrow) * 64) + cc;
        #pragma unroll
        for (int np = 0; np < 2; np++)
            offB[np][ks] = (uint32_t)((nwq * 32 + np * 16 + lrow) * 64) + cc;
    }

    float acc[2][4][4];   // [mi][np*2+hf][quad]
    #pragma unroll
    for (int i = 0; i < 2; i++)
        #pragma unroll
        for (int j = 0; j < 4; j++)
            #pragma unroll
            for (int q = 0; q < 4; q++) acc[i][j][q] = 0.f;

    // prologue: chunks 0,1 -> stages 0,1
    #pragma unroll
    for (int st = 0; st < 2; st++) {
        const uint32_t base = sb + st * GSTG;
        const int ke = st * 32;
        CP_ASYNC16(base + ldstA,        rAh + ke + lcA * 8);
        CP_ASYNC16(base + 4096 + ldstA, rAl + ke + lcA * 8);
        #pragma unroll
        for (int j = 0; j < 2; j++)
            CP_ASYNC16(base + 8192 + ldstB[j], rB + ke + (lc0B + j) * 8);
        CP_COMMIT();
    }

    int stage = 0;
    for (int kc = 0; kc < 32; kc++) {
        // prefetch chunk kc+2 into stage (kc-1)%3 (WAR-safe via end barrier)
        if (kc + 2 < 32) {
            const uint32_t base = sb + ((stage + 2) % 3) * GSTG;
            const int ke = (kc + 2) * 32;
            CP_ASYNC16(base + ldstA,        rAh + ke + lcA * 8);
            CP_ASYNC16(base + 4096 + ldstA, rAl + ke + lcA * 8);
            #pragma unroll
            for (int j = 0; j < 2; j++)
                CP_ASYNC16(base + 8192 + ldstB[j], rB + ke + (lc0B + j) * 8);
            CP_COMMIT();
            CP_WAIT2();      // retire own group for chunk kc
        } else if (kc + 1 < 32) {
            CP_WAIT1();
        } else {
            CP_WAIT0();
        }
        __syncthreads();     // PUBLISH chunk kc to all threads

        const uint32_t B0 = sb + stage * GSTG;
        #pragma unroll
        for (int ks = 0; ks < 2; ks++) {
            uint32_t ah[2][4], al[2][4], bb[2][4];
            ldsm4(ah[0], B0 + offA[0][ks]);
            ldsm4(ah[1], B0 + offA[1][ks]);
            ldsm4(al[0], B0 + 4096 + offA[0][ks]);
            ldsm4(al[1], B0 + 4096 + offA[1][ks]);
            ldsm4(bb[0], B0 + 8192 + offB[0][ks]);
            ldsm4(bb[1], B0 + 8192 + offB[1][ks]);
            // pass 1: Ah x B (8 independent accumulators)
            #pragma unroll
            for (int np = 0; np < 2; np++)
                #pragma unroll
                for (int hf = 0; hf < 2; hf++)
                    #pragma unroll
                    for (int mi = 0; mi < 2; mi++)
                        mma16816(acc[mi][np * 2 + hf], ah[mi],
                                 bb[np][hf], bb[np][hf + 2]);
            // pass 2: Al x B
            #pragma unroll
            for (int np = 0; np < 2; np++)
                #pragma unroll
                for (int hf = 0; hf < 2; hf++)
                    #pragma unroll
                    for (int mi = 0; mi < 2; mi++)
                        mma16816(acc[mi][np * 2 + hf], al[mi],
                                 bb[np][hf], bb[np][hf + 2]);
        }
        __syncthreads();     // WAR: protect stage kc%3 before next prefetch
        stage = (stage + 1) % 3;
    }

    const int tg = lane >> 2, tq = lane & 3;
    #pragma unroll
    for (int mi = 0; mi < 2; mi++) {
        const int gr = bm * 64 + mw * 32 + mi * 16 + tg;
        #pragma unroll
        for (int nj = 0; nj < 4; nj++) {
            const int gc = bn * 128 + nwq * 32 + nj * 8 + tq * 2;
            const float b0 = bias[gc], b1 = bias[gc + 1];
            float* c = acc[mi][nj];
            const float v0 = (c[0] + b0) * scale, v1 = (c[1] + b1) * scale;
            const float v2 = (c[2] + b0) * scale, v3 = (c[3] + b1) * scale;
            if (F32OUT) {
                *(float2*)(Cf + (size_t)gr * DD + gc)       = make_float2(v0, v1);
                *(float2*)(Cf + (size_t)(gr + 8) * DD + gc) = make_float2(v2, v3);
            } else {
                uint32_t h, l;
                splitpack(v0, v1, h, l);
                *(uint32_t*)(Ch + (size_t)gr * DD + gc) = h;
                *(uint32_t*)(Cl + (size_t)gr * DD + gc) = l;
                splitpack(v2, v3, h, l);
                *(uint32_t*)(Ch + (size_t)(gr + 8) * DD + gc) = h;
                *(uint32_t*)(Cl + (size_t)(gr + 8) * DD + gc) = l;
            }
        }
    }
}

template<bool F32OUT>
__global__ __launch_bounds__(256, 3)
void gemm_fp16_kernel(const fp16* __restrict__ Ah, const fp16* __restrict__ Al,
                      const fp16* __restrict__ B,
                      const float* __restrict__ bias, float scale,
                      fp16* __restrict__ Ch, fp16* __restrict__ Cl,
                      float* __restrict__ Cf)
{
    gemm_body<F32OUT>(Ah, Al, B, bias, scale, Ch, Cl, Cf,
                      blockIdx.y, blockIdx.x);
}

// fused Q/K projection: z=0 -> Q (scaled), z=1 -> K
__global__ __launch_bounds__(256, 3)
void qk_gemm_kernel(
    const fp16* iqh, const fp16* iql, const fp16* ikh, const fp16* ikl,
    const fp16* wq, const fp16* wk,
    const float* bq, const float* bk,
    fp16* qh, fp16* ql, fp16* kh, fp16* kl)
{
    if (blockIdx.z == 0)
        gemm_body<false>(iqh, iql, wq, bq, 0.125f, qh, ql, nullptr,
                         blockIdx.y, blockIdx.x);
    else
        gemm_body<false>(ikh, ikl, wk, bk, 1.0f, kh, kl, nullptr,
                         blockIdx.y, blockIdx.x);
}

// ============================================================================
// flash attention: fp16 hi/lo, 3-pass, SW128, 2-stage KV.
// Structure identical to the passing R9/R13 flash (sync always correct here).
// ============================================================================
#define FKV0 32768
#define FKVSTG 32768
#define FLASH_SMEM 98304

__global__ __launch_bounds__(256, 2)
void flash_kernel(const fp16* __restrict__ Qh, const fp16* __restrict__ Ql,
                  const fp16* __restrict__ Kh, const fp16* __restrict__ Kl,
                  const fp16* __restrict__ Vh, const fp16* __restrict__ Vl,
                  fp16* __restrict__ Oh, fp16* __restrict__ Ol)
{
    extern __shared__ char smem[];
    const uint32_t sb = smem_u32(smem);
    const int tid = threadIdx.x, wid = tid >> 5, lane = tid & 31;
    const int qt = (gridDim.x - 1) - blockIdx.x;
    const int h = blockIdx.y, b = blockIdx.z;
    const size_t hbase = ((size_t)b * SS) * DD + h * HDIM;
    const int nkt = 2 * qt + 2;

    const int qlr = tid >> 1, qc0 = (tid & 1) * 4;
    const int klr = tid >> 2, kc0 = (tid & 3) * 2;
    const fp16* rQh = Qh + hbase + (size_t)(qt * 128 + qlr) * DD;
    const fp16* rQl = Ql + hbase + (size_t)(qt * 128 + qlr) * DD;
    const fp16* rKh = Kh + hbase + (size_t)klr * DD;
    const fp16* rKl = Kl + hbase + (size_t)klr * DD;
    const fp16* rVh = Vh + hbase + (size_t)klr * DD;
    const fp16* rVl = Vl + hbase + (size_t)klr * DD;
    const uint32_t qx = qlr & 7, kx = klr & 7;

    #pragma unroll
    for (int j = 0; j < 4; j++) {
        const uint32_t d = (uint32_t)(qlr * 128 + ((qc0 + j) ^ qx) * 16);
        const int eo = (qc0 + j) * 8;
        CP_ASYNC16(sb + d,         rQh + eo);
        CP_ASYNC16(sb + 16384 + d, rQl + eo);
    }
    #pragma unroll
    for (int j = 0; j < 2; j++) {
        const uint32_t d = (uint32_t)(klr * 128 + ((kc0 + j) ^ kx) * 16);
        const int eo = (kc0 + j) * 8;
        CP_ASYNC16(sb + FKV0 + d,         rKh + eo);
        CP_ASYNC16(sb + FKV0 + 8192 + d,  rKl + eo);
        CP_ASYNC16(sb + FKV0 + 16384 + d, rVh + eo);
        CP_ASYNC16(sb + FKV0 + 24576 + d, rVl + eo);
    }
    CP_COMMIT();

    const int lrow = lane & 15, cl = lane >> 4;
    const uint32_t x = lrow & 7;
    const uint32_t rb = (uint32_t)(lrow * 128);
    const uint32_t qwb = (uint32_t)(wid * 2048);

    float oacc[8][4];
    #pragma unroll
    for (int t = 0; t < 8; t++)
        #pragma unroll
        for (int j = 0; j < 4; j++) oacc[t][j] = 0.f;
    float m0 = -1e30f, m1 = -1e30f, l0 = 0.f, l1 = 0.f;

    for (int kt = 0; kt < nkt; kt++) {
        if (kt + 1 < nkt) {
            const uint32_t base = sb + FKV0 + ((kt + 1) & 1) * FKVSTG;
            const size_t ro = (size_t)(kt + 1) * 64 * DD;
            #pragma unroll
            for (int j = 0; j < 2; j++) {
                const uint32_t d = (uint32_t)(klr * 128 + ((kc0 + j) ^ kx) * 16);
                const int eo = (kc0 + j) * 8;
                CP_ASYNC16(base + d,         rKh + ro + eo);
                CP_ASYNC16(base + 8192 + d,  rKl + ro + eo);
                CP_ASYNC16(base + 16384 + d, rVh + ro + eo);
                CP_ASYNC16(base + 24576 + d, rVl + ro + eo);
            }
            CP_COMMIT();
            CP_WAIT1();
        } else {
            CP_WAIT0();
        }
        __syncthreads();

        const uint32_t kvb = sb + FKV0 + (kt & 1) * FKVSTG;

        float s[8][4];
        #pragma unroll
        for (int t = 0; t < 8; t++)
            #pragma unroll
            for (int j = 0; j < 4; j++) s[t][j] = 0.f;

        #pragma unroll
        for (int ks = 0; ks < 4; ks++) {
            const uint32_t cc = ((uint32_t)(ks * 2 + cl) ^ x) * 16;
            uint32_t qhi[4], qlo[4];
            ldsm4(qhi, sb + qwb + rb + cc);
            ldsm4(qlo, sb + 16384 + qwb + rb + cc);
            #pragma unroll
            for (int np = 0; np < 4; np++) {
                uint32_t khi[4], klo[4];
                const uint32_t ko = kvb + (uint32_t)(np * 2048) + rb + cc;
                ldsm4(khi, ko);
                ldsm4(klo, ko + 8192);
                float* s0 = s[np * 2 + 0];
                float* s1 = s[np * 2 + 1];
                mma16816(s0, qhi, khi[0], khi[2]);
                mma16816(s1, qhi, khi[1], khi[3]);
                mma16816(s0, qhi, klo[0], klo[2]);
                mma16816(s1, qhi, klo[1], klo[3]);
                mma16816(s0, qlo, khi[0], khi[2]);
                mma16816(s1, qlo, khi[1], khi[3]);
            }
        }

        if (kt >= 2 * qt) {
            const int off = (kt - 2 * qt) * 64;
            const int r0 = wid * 16 + (lane >> 2);
            const int cb = (lane & 3) * 2;
            #pragma unroll
            for (int t = 0; t < 8; t++)
                #pragma unroll
                for (int j = 0; j < 2; j++) {
                    const int cg = off + t * 8 + cb + j;
                    if (cg > r0)     s[t][j]     = -1e30f;
                    if (cg > r0 + 8) s[t][2 + j] = -1e30f;
                }
        }

        float mx0 = -1e30f, mx1 = -1e30f;
        #pragma unroll
        for (int t = 0; t < 8; t++) {
            mx0 = fmaxf(mx0, fmaxf(s[t][0], s[t][1]));
            mx1 = fmaxf(mx1, fmaxf(s[t][2], s[t][3]));
        }
        mx0 = fmaxf(mx0, __shfl_xor_sync(0xffffffffu, mx0, 1));
        mx0 = fmaxf(mx0, __shfl_xor_sync(0xffffffffu, mx0, 2));
        mx1 = fmaxf(mx1, __shfl_xor_sync(0xffffffffu, mx1, 1));
        mx1 = fmaxf(mx1, __shfl_xor_sync(0xffffffffu, mx1, 2));

        const float mn0 = fmaxf(m0, mx0);
        const float mn1 = fmaxf(m1, mx1);
        const float al0 = __expf(m0 - mn0);
        const float al1 = __expf(m1 - mn1);
        m0 = mn0; m1 = mn1;

        float ls0 = 0.f, ls1 = 0.f;
        #pragma unroll
        for (int t = 0; t < 8; t++) {
            s[t][0] = __expf(s[t][0] - mn0); ls0 += s[t][0];
            s[t][1] = __expf(s[t][1] - mn0); ls0 += s[t][1];
            s[t][2] = __expf(s[t][2] - mn1); ls1 += s[t][2];
            s[t][3] = __expf(s[t][3] - mn1); ls1 += s[t][3];
        }
        ls0 += __shfl_xor_sync(0xffffffffu, ls0, 1);
        ls0 += __shfl_xor_sync(0xffffffffu, ls0, 2);
        ls1 += __shfl_xor_sync(0xffffffffu, ls1, 1);
        ls1 += __shfl_xor_sync(0xffffffffu, ls1, 2);
        l0 = l0 * al0 + ls0;
        l1 = l1 * al1 + ls1;
        #pragma unroll
        for (int t = 0; t < 8; t++) {
            oacc[t][0] *= al0; oacc[t][1] *= al0;
            oacc[t][2] *= al1; oacc[t][3] *= al1;
        }

        #pragma unroll
        for (int t = 0; t < 4; t++) {
            uint32_t aPhi[4], aPlo[4];
            splitpack(s[2 * t][0],     s[2 * t][1],     aPhi[0], aPlo[0]);
            splitpack(s[2 * t][2],     s[2 * t][3],     aPhi[1], aPlo[1]);
            splitpack(s[2 * t + 1][0], s[2 * t + 1][1], aPhi[2], aPlo[2]);
            splitpack(s[2 * t + 1][2], s[2 * t + 1][3], aPhi[3], aPlo[3]);
            #pragma unroll
            for (int np = 0; np < 4; np++) {
                const uint32_t cc = ((uint32_t)(np * 2 + cl) ^ x) * 16;
                const uint32_t vo = kvb + 16384 + (uint32_t)(t * 2048) + rb + cc;
                uint32_t vhi[4], vlo[4];
                ldsm4t(vhi, vo);
                ldsm4t(vlo, vo + 8192);
                float* o0 = oacc[np * 2 + 0];
                float* o1 = oacc[np * 2 + 1];
                mma16816(o0, aPhi, vhi[0], vhi[1]);
                mma16816(o1, aPhi, vhi[2], vhi[3]);
                mma16816(o0, aPhi, vlo[0], vlo[1]);
                mma16816(o1, aPhi, vlo[2], vlo[3]);
                mma16816(o0, aPlo, vhi[0], vhi[1]);
                mma16816(o1, aPlo, vhi[2], vhi[3]);
            }
        }
        __syncthreads();
    }

    const float inv0 = 1.0f / l0;
    const float inv1 = 1.0f / l1;
    const int r0 = qt * 128 + wid * 16 + (lane >> 2);
    const int cb = (lane & 3) * 2;
    #pragma unroll
    for (int t = 0; t < 8; t++) {
        uint32_t h0, lo0, h1, lo1;
        splitpack(oacc[t][0] * inv0, oacc[t][1] * inv0, h0, lo0);
        splitpack(oacc[t][2] * inv1, oacc[t][3] * inv1, h1, lo1);
        const size_t o0 = hbase + (size_t)r0 * DD + t * 8 + cb;
        const size_t o1 = hbase + (size_t)(r0 + 8) * DD + t * 8 + cb;
        *(uint32_t*)(Oh + o0) = h0;
        *(uint32_t*)(Ol + o0) = lo0;
        *(uint32_t*)(Oh + o1) = h1;
        *(uint32_t*)(Ol + o1) = lo1;
    }
}

// ---------------- launch ----------------
extern "C" void kernel_launch(void* const* d_in, const int* in_sizes, int n_in,
                              void* d_out, int out_size)
{
    const float* queries = (const float*)d_in[0];
    const float* keys    = (const float*)d_in[1];
    const float* Wq = (const float*)d_in[4];
    const float* bq = (const float*)d_in[5];
    const float* Wk = (const float*)d_in[6];
    const float* bk = (const float*)d_in[7];
    const float* Wv = (const float*)d_in[8];
    const float* bv = (const float*)d_in[9];
    const float* Wo = (const float*)d_in[10];
    const float* bo = (const float*)d_in[11];
    float* out = (float*)d_out;

    fp16 *inqh, *inql, *inkh, *inkl;
    fp16 *wq16, *wk16, *wv16, *wo16;
    fp16 *qh, *ql, *kh, *kl, *vh, *vl, *ah, *al;
    cudaGetSymbolAddress((void**)&inqh, g_inqh); cudaGetSymbolAddress((void**)&inql, g_inql);
    cudaGetSymbolAddress((void**)&inkh, g_inkh); cudaGetSymbolAddress((void**)&inkl, g_inkl);
    cudaGetSymbolAddress((void**)&wq16, g_wq16); cudaGetSymbolAddress((void**)&wk16, g_wk16);
    cudaGetSymbolAddress((void**)&wv16, g_wv16); cudaGetSymbolAddress((void**)&wo16, g_wo16);
    cudaGetSymbolAddress((void**)&qh, g_qh); cudaGetSymbolAddress((void**)&ql, g_ql);
    cudaGetSymbolAddress((void**)&kh, g_kh); cudaGetSymbolAddress((void**)&kl, g_kl);
    cudaGetSymbolAddress((void**)&vh, g_vh); cudaGetSymbolAddress((void**)&vl, g_vl);
    cudaGetSymbolAddress((void**)&ah, g_ah); cudaGetSymbolAddress((void**)&al, g_al);

    cudaFuncSetAttribute(gemm_fp16_kernel<false>,
                         cudaFuncAttributeMaxDynamicSharedMemorySize, GEMM_SMEM);
    cudaFuncSetAttribute(gemm_fp16_kernel<true>,
                         cudaFuncAttributeMaxDynamicSharedMemorySize, GEMM_SMEM);
    cudaFuncSetAttribute(qk_gemm_kernel,
                         cudaFuncAttributeMaxDynamicSharedMemorySize, GEMM_SMEM);
    cudaFuncSetAttribute(flash_kernel,
                         cudaFuncAttributeMaxDynamicSharedMemorySize, FLASH_SMEM);

    // 1) splits (launches 1-2)
    const int selem = MROWS * DD;
    dim3 sgrid(selem / 1024, 1, 2);
    split_fused_kernel<<<sgrid, 256>>>(queries, inqh, inql, keys, inkh, inkl);
    dim3 wtb(32, 8), wtg(32, 32, 4);
    splitw_fused_kernel<<<wtg, wtb>>>(Wq, wq16, Wk, wk16, Wv, wv16, Wo, wo16);

    // 2) fused Q+K projections (launch 3; 1024 CTAs of 64x128)
    dim3 gblk(256);
    dim3 qkgrid(DD / 128, MROWS / 64, 2);
    qk_gemm_kernel<<<qkgrid, gblk, GEMM_SMEM>>>(
        inqh, inql, inkh, inkl, wq16, wk16, bq, bk, qh, ql, kh, kl);

    // 3) V projection from projected K (launch 4; 512 CTAs)
    dim3 ggrid(DD / 128, MROWS / 64);
    gemm_fp16_kernel<false><<<ggrid, gblk, GEMM_SMEM>>>(
        kh, kl, wv16, bv, 1.0f, vh, vl, nullptr);

    // 4) attention (launch 5)
    dim3 fgrid(SS / 128, HH, BB);
    flash_kernel<<<fgrid, dim3(256), FLASH_SMEM>>>(qh, ql, kh, kl, vh, vl, ah, al);

    // 5) output projection (launch 6 -> profiled by ncu -s 5 -c 1)
    gemm_fp16_kernel<true><<<ggrid, gblk, GEMM_SMEM>>>(
        ah, al, wo16, bo, 1.0f, nullptr, nullptr, out);
}

// round 15
// speedup vs baseline: 1.4293x; 1.1320x over previous
#include <cuda_runtime.h>
#include <cuda_fp16.h>
#include <cstdint>

// Problem constants
#define BB   2
#define SS   2048
#define DD   1024
#define HH   16
#define HDIM 64
#define MROWS (BB*SS)      // 4096
typedef __half fp16;

// ---------------- scratch (no allocations allowed) ----------------
__device__ fp16 g_inqh[MROWS * DD], g_inql[MROWS * DD];
__device__ fp16 g_inkh[MROWS * DD], g_inkl[MROWS * DD];
__device__ fp16 g_wq16[DD * DD];   // W^T [n][k] single fp16
__device__ fp16 g_wk16[DD * DD];
__device__ fp16 g_wv16[DD * DD];
__device__ fp16 g_wo16[DD * DD];
__device__ fp16 g_qh[MROWS * DD], g_ql[MROWS * DD];
__device__ fp16 g_kh[MROWS * DD], g_kl[MROWS * DD];
__device__ fp16 g_vh[MROWS * DD], g_vl[MROWS * DD];
__device__ fp16 g_ah[MROWS * DD], g_al[MROWS * DD];

// ============================================================================
// helpers
// ============================================================================
__device__ __forceinline__ uint32_t smem_u32(const void* p) {
    uint32_t a;
    asm("{ .reg .u64 t; cvta.to.shared.u64 t, %1; cvt.u32.u64 %0, t; }"
        : "=r"(a) : "l"(p));
    return a;
}
__device__ __forceinline__ void ldsm4(uint32_t* r, uint32_t addr) {
    asm volatile("ldmatrix.sync.aligned.m8n8.x4.shared.b16 {%0,%1,%2,%3}, [%4];"
                 : "=r"(r[0]), "=r"(r[1]), "=r"(r[2]), "=r"(r[3]) : "r"(addr));
}
__device__ __forceinline__ void ldsm4t(uint32_t* r, uint32_t addr) {
    asm volatile("ldmatrix.sync.aligned.m8n8.x4.trans.shared.b16 {%0,%1,%2,%3}, [%4];"
                 : "=r"(r[0]), "=r"(r[1]), "=r"(r[2]), "=r"(r[3]) : "r"(addr));
}
// fp16 mma with fp32 accumulate
__device__ __forceinline__ void mma16816(float* c, const uint32_t* a,
                                         uint32_t b0, uint32_t b1) {
    asm volatile(
        "mma.sync.aligned.m16n8k16.row.col.f32.f16.f16.f32 "
        "{%0,%1,%2,%3}, {%4,%5,%6,%7}, {%8,%9}, {%0,%1,%2,%3};"
        : "+f"(c[0]), "+f"(c[1]), "+f"(c[2]), "+f"(c[3])
        : "r"(a[0]), "r"(a[1]), "r"(a[2]), "r"(a[3]), "r"(b0), "r"(b1));
}
__device__ __forceinline__ void splitpack(float x, float y, uint32_t& hi, uint32_t& lo) {
    fp16 hx = __float2half_rn(x), hy = __float2half_rn(y);
    float rx = x - __half2float(hx);
    float ry = y - __half2float(hy);
    fp16 lx = __float2half_rn(rx), ly = __float2half_rn(ry);
    hi = (uint32_t)__half_as_ushort(hx) | ((uint32_t)__half_as_ushort(hy) << 16);
    lo = (uint32_t)__half_as_ushort(lx) | ((uint32_t)__half_as_ushort(ly) << 16);
}

#define CP_ASYNC16(dst, src) \
    asm volatile("cp.async.cg.shared.global [%0], [%1], 16;" \
                 :: "r"(dst), "l"(src) : "memory")
#define CP_COMMIT() asm volatile("cp.async.commit_group;" ::: "memory")
#define CP_WAIT0()  asm volatile("cp.async.wait_group 0;" ::: "memory")
#define CP_WAIT1()  asm volatile("cp.async.wait_group 1;" ::: "memory")
#define CP_WAIT2()  asm volatile("cp.async.wait_group 2;" ::: "memory")

// ============================================================================
// split kernels
// ============================================================================
__global__ void split_fused_kernel(const float* __restrict__ s0, fp16* h0, fp16* l0,
                                   const float* __restrict__ s1, fp16* h1, fp16* l1)
{
    const float* src = blockIdx.z ? s1 : s0;
    fp16* hi = blockIdx.z ? h1 : h0;
    fp16* lo = blockIdx.z ? l1 : l0;
    const int i = (blockIdx.x * 256 + threadIdx.x) * 4;
    float4 v = *(const float4*)(src + i);
    uint32_t a0, b0, a1, b1;
    splitpack(v.x, v.y, a0, b0);
    splitpack(v.z, v.w, a1, b1);
    *(uint2*)(hi + i) = make_uint2(a0, a1);
    *(uint2*)(lo + i) = make_uint2(b0, b1);
}

// W [k][n] fp32 -> Wt [n][k] single fp16, smem tile transpose; z selects matrix
__global__ void splitw_fused_kernel(
    const float* __restrict__ W0, fp16* t0,
    const float* __restrict__ W1, fp16* t1,
    const float* __restrict__ W2, fp16* t2,
    const float* __restrict__ W3, fp16* t3)
{
    const float* W; fp16* th;
    switch (blockIdx.z) {
        case 0: W = W0; th = t0; break;
        case 1: W = W1; th = t1; break;
        case 2: W = W2; th = t2; break;
        default: W = W3; th = t3; break;
    }
    __shared__ float t[32][33];
    const int tx = threadIdx.x, ty = threadIdx.y;
    const int k0 = blockIdx.y * 32, n0 = blockIdx.x * 32;
    #pragma unroll
    for (int i = 0; i < 4; i++)
        t[ty + i * 8][tx] = W[(size_t)(k0 + ty + i * 8) * DD + n0 + tx];
    __syncthreads();
    #pragma unroll
    for (int i = 0; i < 4; i++)
        th[(size_t)(n0 + ty + i * 8) * DD + k0 + tx] =
            __float2half_rn(t[tx][ty + i * 8]);
}

// ============================================================================
// GEMM (unchanged from passing R14): CTA 64x128, A fp16 hi/lo 2-pass, B single.
// 3-stage cp.async with proven sync. stage: AHI 4K | ALO 4K | B 8K = 16K
// ============================================================================
#define GSTG 16384
#define GEMM_SMEM (3 * GSTG)

template<bool F32OUT>
__device__ __forceinline__ void gemm_body(
    const fp16* __restrict__ Ah, const fp16* __restrict__ Al,
    const fp16* __restrict__ B,
    const float* __restrict__ bias, float scale,
    fp16* __restrict__ Ch, fp16* __restrict__ Cl, float* __restrict__ Cf,
    int bm, int bn)
{
    extern __shared__ char smem[];
    const uint32_t sb = smem_u32(smem);
    const int tid = threadIdx.x, wid = tid >> 5, lane = tid & 31;
    const int mw = wid >> 2;
    const int nwq = wid & 3;

    const int lrA = tid >> 2, lcA = tid & 3;
    const fp16* rAh = Ah + (size_t)(bm * 64 + lrA) * DD;
    const fp16* rAl = Al + (size_t)(bm * 64 + lrA) * DD;
    const uint32_t ldstA = (uint32_t)(lrA * 64 + (lcA ^ ((lrA >> 1) & 3)) * 16);
    const int lrB = tid >> 1, lc0B = (tid & 1) * 2;
    const fp16* rB = B + (size_t)(bn * 128 + lrB) * DD;
    const uint32_t xlB = (lrB >> 1) & 3;
    uint32_t ldstB[2];
    #pragma unroll
    for (int j = 0; j < 2; j++)
        ldstB[j] = (uint32_t)(lrB * 64 + ((lc0B + j) ^ xlB) * 16);

    const int lrow = lane & 15, cl = lane >> 4;
    const uint32_t xg = (lrow >> 1) & 3;
    uint32_t offA[2][2], offB[2][2];
    #pragma unroll
    for (int ks = 0; ks < 2; ks++) {
        const uint32_t cc = (uint32_t)(((ks * 2 + cl) ^ xg) * 16);
        #pragma unroll
        for (int mi = 0; mi < 2; mi++)
            offA[mi][ks] = (uint32_t)((mw * 32 + mi * 16 + lrow) * 64) + cc;
        #pragma unroll
        for (int np = 0; np < 2; np++)
            offB[np][ks] = (uint32_t)((nwq * 32 + np * 16 + lrow) * 64) + cc;
    }

    float acc[2][4][4];
    #pragma unroll
    for (int i = 0; i < 2; i++)
        #pragma unroll
        for (int j = 0; j < 4; j++)
            #pragma unroll
            for (int q = 0; q < 4; q++) acc[i][j][q] = 0.f;

    #pragma unroll
    for (int st = 0; st < 2; st++) {
        const uint32_t base = sb + st * GSTG;
        const int ke = st * 32;
        CP_ASYNC16(base + ldstA,        rAh + ke + lcA * 8);
        CP_ASYNC16(base + 4096 + ldstA, rAl + ke + lcA * 8);
        #pragma unroll
        for (int j = 0; j < 2; j++)
            CP_ASYNC16(base + 8192 + ldstB[j], rB + ke + (lc0B + j) * 8);
        CP_COMMIT();
    }

    int stage = 0;
    for (int kc = 0; kc < 32; kc++) {
        if (kc + 2 < 32) {
            const uint32_t base = sb + ((stage + 2) % 3) * GSTG;
            const int ke = (kc + 2) * 32;
            CP_ASYNC16(base + ldstA,        rAh + ke + lcA * 8);
            CP_ASYNC16(base + 4096 + ldstA, rAl + ke + lcA * 8);
            #pragma unroll
            for (int j = 0; j < 2; j++)
                CP_ASYNC16(base + 8192 + ldstB[j], rB + ke + (lc0B + j) * 8);
            CP_COMMIT();
            CP_WAIT2();
        } else if (kc + 1 < 32) {
            CP_WAIT1();
        } else {
            CP_WAIT0();
        }
        __syncthreads();     // PUBLISH

        const uint32_t B0 = sb + stage * GSTG;
        #pragma unroll
        for (int ks = 0; ks < 2; ks++) {
            uint32_t ah[2][4], al[2][4], bb[2][4];
            ldsm4(ah[0], B0 + offA[0][ks]);
            ldsm4(ah[1], B0 + offA[1][ks]);
            ldsm4(al[0], B0 + 4096 + offA[0][ks]);
            ldsm4(al[1], B0 + 4096 + offA[1][ks]);
            ldsm4(bb[0], B0 + 8192 + offB[0][ks]);
            ldsm4(bb[1], B0 + 8192 + offB[1][ks]);
            #pragma unroll
            for (int np = 0; np < 2; np++)
                #pragma unroll
                for (int hf = 0; hf < 2; hf++)
                    #pragma unroll
                    for (int mi = 0; mi < 2; mi++)
                        mma16816(acc[mi][np * 2 + hf], ah[mi],
                                 bb[np][hf], bb[np][hf + 2]);
            #pragma unroll
            for (int np = 0; np < 2; np++)
                #pragma unroll
                for (int hf = 0; hf < 2; hf++)
                    #pragma unroll
                    for (int mi = 0; mi < 2; mi++)
                        mma16816(acc[mi][np * 2 + hf], al[mi],
                                 bb[np][hf], bb[np][hf + 2]);
        }
        __syncthreads();     // WAR
        stage = (stage + 1) % 3;
    }

    const int tg = lane >> 2, tq = lane & 3;
    #pragma unroll
    for (int mi = 0; mi < 2; mi++) {
        const int gr = bm * 64 + mw * 32 + mi * 16 + tg;
        #pragma unroll
        for (int nj = 0; nj < 4; nj++) {
            const int gc = bn * 128 + nwq * 32 + nj * 8 + tq * 2;
            const float b0 = bias[gc], b1 = bias[gc + 1];
            float* c = acc[mi][nj];
            const float v0 = (c[0] + b0) * scale, v1 = (c[1] + b1) * scale;
            const float v2 = (c[2] + b0) * scale, v3 = (c[3] + b1) * scale;
            if (F32OUT) {
                *(float2*)(Cf + (size_t)gr * DD + gc)       = make_float2(v0, v1);
                *(float2*)(Cf + (size_t)(gr + 8) * DD + gc) = make_float2(v2, v3);
            } else {
                uint32_t h, l;
                splitpack(v0, v1, h, l);
                *(uint32_t*)(Ch + (size_t)gr * DD + gc) = h;
                *(uint32_t*)(Cl + (size_t)gr * DD + gc) = l;
                splitpack(v2, v3, h, l);
                *(uint32_t*)(Ch + (size_t)(gr + 8) * DD + gc) = h;
                *(uint32_t*)(Cl + (size_t)(gr + 8) * DD + gc) = l;
            }
        }
    }
}

template<bool F32OUT>
__global__ __launch_bounds__(256, 3)
void gemm_fp16_kernel(const fp16* __restrict__ Ah, const fp16* __restrict__ Al,
                      const fp16* __restrict__ B,
                      const float* __restrict__ bias, float scale,
                      fp16* __restrict__ Ch, fp16* __restrict__ Cl,
                      float* __restrict__ Cf)
{
    gemm_body<F32OUT>(Ah, Al, B, bias, scale, Ch, Cl, Cf,
                      blockIdx.y, blockIdx.x);
}

__global__ __launch_bounds__(256, 3)
void qk_gemm_kernel(
    const fp16* iqh, const fp16* iql, const fp16* ikh, const fp16* ikl,
    const fp16* wq, const fp16* wk,
    const float* bq, const float* bk,
    fp16* qh, fp16* ql, fp16* kh, fp16* kl)
{
    if (blockIdx.z == 0)
        gemm_body<false>(iqh, iql, wq, bq, 0.125f, qh, ql, nullptr,
                         blockIdx.y, blockIdx.x);
    else
        gemm_body<false>(ikh, ikl, wk, bk, 1.0f, kh, kl, nullptr,
                         blockIdx.y, blockIdx.x);
}

// ============================================================================
// flash attention v3: Q fp16 hi/lo (exact), K and V SINGLE fp16 (B-operand
// trick). QK = 2 passes, PV = 2 passes (P hi/lo). SW128, 2-stage KV.
// smem: QHI 16K | QLO 16K | stage{K 8K | V 8K} x2 = 64K.
// ============================================================================
#define FKV0 32768
#define FKVSTG 16384
#define FLASH_SMEM 65536

__global__ __launch_bounds__(256, 2)
void flash_kernel(const fp16* __restrict__ Qh, const fp16* __restrict__ Ql,
                  const fp16* __restrict__ Kh, const fp16* __restrict__ Vh,
                  fp16* __restrict__ Oh, fp16* __restrict__ Ol)
{
    extern __shared__ char smem[];
    const uint32_t sb = smem_u32(smem);
    const int tid = threadIdx.x, wid = tid >> 5, lane = tid & 31;
    const int qt = (gridDim.x - 1) - blockIdx.x;
    const int h = blockIdx.y, b = blockIdx.z;
    const size_t hbase = ((size_t)b * SS) * DD + h * HDIM;
    const int nkt = 2 * qt + 2;

    const int qlr = tid >> 1, qc0 = (tid & 1) * 4;
    const int klr = tid >> 2, kc0 = (tid & 3) * 2;
    const fp16* rQh = Qh + hbase + (size_t)(qt * 128 + qlr) * DD;
    const fp16* rQl = Ql + hbase + (size_t)(qt * 128 + qlr) * DD;
    const fp16* rKh = Kh + hbase + (size_t)klr * DD;
    const fp16* rVh = Vh + hbase + (size_t)klr * DD;
    const uint32_t qx = qlr & 7, kx = klr & 7;

    #pragma unroll
    for (int j = 0; j < 4; j++) {
        const uint32_t d = (uint32_t)(qlr * 128 + ((qc0 + j) ^ qx) * 16);
        const int eo = (qc0 + j) * 8;
        CP_ASYNC16(sb + d,         rQh + eo);
        CP_ASYNC16(sb + 16384 + d, rQl + eo);
    }
    #pragma unroll
    for (int j = 0; j < 2; j++) {
        const uint32_t d = (uint32_t)(klr * 128 + ((kc0 + j) ^ kx) * 16);
        const int eo = (kc0 + j) * 8;
        CP_ASYNC16(sb + FKV0 + d,        rKh + eo);
        CP_ASYNC16(sb + FKV0 + 8192 + d, rVh + eo);
    }
    CP_COMMIT();

    const int lrow = lane & 15, cl = lane >> 4;
    const uint32_t x = lrow & 7;
    const uint32_t rb = (uint32_t)(lrow * 128);
    const uint32_t qwb = (uint32_t)(wid * 2048);

    float oacc[8][4];
    #pragma unroll
    for (int t = 0; t < 8; t++)
        #pragma unroll
        for (int j = 0; j < 4; j++) oacc[t][j] = 0.f;
    float m0 = -1e30f, m1 = -1e30f, l0 = 0.f, l1 = 0.f;

    for (int kt = 0; kt < nkt; kt++) {
        if (kt + 1 < nkt) {
            const uint32_t base = sb + FKV0 + ((kt + 1) & 1) * FKVSTG;
            const size_t ro = (size_t)(kt + 1) * 64 * DD;
            #pragma unroll
            for (int j = 0; j < 2; j++) {
                const uint32_t d = (uint32_t)(klr * 128 + ((kc0 + j) ^ kx) * 16);
                const int eo = (kc0 + j) * 8;
                CP_ASYNC16(base + d,        rKh + ro + eo);
                CP_ASYNC16(base + 8192 + d, rVh + ro + eo);
            }
            CP_COMMIT();
            CP_WAIT1();
        } else {
            CP_WAIT0();
        }
        __syncthreads();

        const uint32_t kvb = sb + FKV0 + (kt & 1) * FKVSTG;

        float s[8][4];
        #pragma unroll
        for (int t = 0; t < 8; t++)
            #pragma unroll
            for (int j = 0; j < 4; j++) s[t][j] = 0.f;

        // S = Q K^T : 2 passes (qhi + qlo) over single-fp16 K
        #pragma unroll
        for (int ks = 0; ks < 4; ks++) {
            const uint32_t cc = ((uint32_t)(ks * 2 + cl) ^ x) * 16;
            uint32_t qhi[4], qlo[4];
            ldsm4(qhi, sb + qwb + rb + cc);
            ldsm4(qlo, sb + 16384 + qwb + rb + cc);
            #pragma unroll
            for (int np = 0; np < 4; np++) {
                uint32_t kk[4];
                ldsm4(kk, kvb + (uint32_t)(np * 2048) + rb + cc);
                float* s0 = s[np * 2 + 0];
                float* s1 = s[np * 2 + 1];
                mma16816(s0, qhi, kk[0], kk[2]);
                mma16816(s1, qhi, kk[1], kk[3]);
                mma16816(s0, qlo, kk[0], kk[2]);
                mma16816(s1, qlo, kk[1], kk[3]);
            }
        }

        if (kt >= 2 * qt) {
            const int off = (kt - 2 * qt) * 64;
            const int r0 = wid * 16 + (lane >> 2);
            const int cb = (lane & 3) * 2;
            #pragma unroll
            for (int t = 0; t < 8; t++)
                #pragma unroll
                for (int j = 0; j < 2; j++) {
                    const int cg = off + t * 8 + cb + j;
                    if (cg > r0)     s[t][j]     = -1e30f;
                    if (cg > r0 + 8) s[t][2 + j] = -1e30f;
                }
        }

        float mx0 = -1e30f, mx1 = -1e30f;
        #pragma unroll
        for (int t = 0; t < 8; t++) {
            mx0 = fmaxf(mx0, fmaxf(s[t][0], s[t][1]));
            mx1 = fmaxf(mx1, fmaxf(s[t][2], s[t][3]));
        }
        mx0 = fmaxf(mx0, __shfl_xor_sync(0xffffffffu, mx0, 1));
        mx0 = fmaxf(mx0, __shfl_xor_sync(0xffffffffu, mx0, 2));
        mx1 = fmaxf(mx1, __shfl_xor_sync(0xffffffffu, mx1, 1));
        mx1 = fmaxf(mx1, __shfl_xor_sync(0xffffffffu, mx1, 2));

        const float mn0 = fmaxf(m0, mx0);
        const float mn1 = fmaxf(m1, mx1);
        const float al0 = __expf(m0 - mn0);
        const float al1 = __expf(m1 - mn1);
        m0 = mn0; m1 = mn1;

        float ls0 = 0.f, ls1 = 0.f;
        #pragma unroll
        for (int t = 0; t < 8; t++) {
            s[t][0] = __expf(s[t][0] - mn0); ls0 += s[t][0];
            s[t][1] = __expf(s[t][1] - mn0); ls0 += s[t][1];
            s[t][2] = __expf(s[t][2] - mn1); ls1 += s[t][2];
            s[t][3] = __expf(s[t][3] - mn1); ls1 += s[t][3];
        }
        ls0 += __shfl_xor_sync(0xffffffffu, ls0, 1);
        ls0 += __shfl_xor_sync(0xffffffffu, ls0, 2);
        ls1 += __shfl_xor_sync(0xffffffffu, ls1, 1);
        ls1 += __shfl_xor_sync(0xffffffffu, ls1, 2);
        l0 = l0 * al0 + ls0;
        l1 = l1 * al1 + ls1;
        #pragma unroll
        for (int t = 0; t < 8; t++) {
            oacc[t][0] *= al0; oacc[t][1] *= al0;
            oacc[t][2] *= al1; oacc[t][3] *= al1;
        }

        // O += P V : 2 passes (phi + plo) over single-fp16 V
        #pragma unroll
        for (int t = 0; t < 4; t++) {
            uint32_t aPhi[4], aPlo[4];
            splitpack(s[2 * t][0],     s[2 * t][1],     aPhi[0], aPlo[0]);
            splitpack(s[2 * t][2],     s[2 * t][3],     aPhi[1], aPlo[1]);
            splitpack(s[2 * t + 1][0], s[2 * t + 1][1], aPhi[2], aPlo[2]);
            splitpack(s[2 * t + 1][2], s[2 * t + 1][3], aPhi[3], aPlo[3]);
            #pragma unroll
            for (int np = 0; np < 4; np++) {
                const uint32_t cc = ((uint32_t)(np * 2 + cl) ^ x) * 16;
                uint32_t vv[4];
                ldsm4t(vv, kvb + 8192 + (uint32_t)(t * 2048) + rb + cc);
                float* o0 = oacc[np * 2 + 0];
                float* o1 = oacc[np * 2 + 1];
                mma16816(o0, aPhi, vv[0], vv[1]);
                mma16816(o1, aPhi, vv[2], vv[3]);
                mma16816(o0, aPlo, vv[0], vv[1]);
                mma16816(o1, aPlo, vv[2], vv[3]);
            }
        }
        __syncthreads();
    }

    const float inv0 = 1.0f / l0;
    const float inv1 = 1.0f / l1;
    const int r0 = qt * 128 + wid * 16 + (lane >> 2);
    const int cb = (lane & 3) * 2;
    #pragma unroll
    for (int t = 0; t < 8; t++) {
        uint32_t h0, lo0, h1, lo1;
        splitpack(oacc[t][0] * inv0, oacc[t][1] * inv0, h0, lo0);
        splitpack(oacc[t][2] * inv1, oacc[t][3] * inv1, h1, lo1);
        const size_t o0 = hbase + (size_t)r0 * DD + t * 8 + cb;
        const size_t o1 = hbase + (size_t)(r0 + 8) * DD + t * 8 + cb;
        *(uint32_t*)(Oh + o0) = h0;
        *(uint32_t*)(Ol + o0) = lo0;
        *(uint32_t*)(Oh + o1) = h1;
        *(uint32_t*)(Ol + o1) = lo1;
    }
}

// ---------------- launch ----------------
extern "C" void kernel_launch(void* const* d_in, const int* in_sizes, int n_in,
                              void* d_out, int out_size)
{
    const float* queries = (const float*)d_in[0];
    const float* keys    = (const float*)d_in[1];
    const float* Wq = (const float*)d_in[4];
    const float* bq = (const float*)d_in[5];
    const float* Wk = (const float*)d_in[6];
    const float* bk = (const float*)d_in[7];
    const float* Wv = (const float*)d_in[8];
    const float* bv = (const float*)d_in[9];
    const float* Wo = (const float*)d_in[10];
    const float* bo = (const float*)d_in[11];
    float* out = (float*)d_out;

    fp16 *inqh, *inql, *inkh, *inkl;
    fp16 *wq16, *wk16, *wv16, *wo16;
    fp16 *qh, *ql, *kh, *kl, *vh, *vl, *ah, *al;
    cudaGetSymbolAddress((void**)&inqh, g_inqh); cudaGetSymbolAddress((void**)&inql, g_inql);
    cudaGetSymbolAddress((void**)&inkh, g_inkh); cudaGetSymbolAddress((void**)&inkl, g_inkl);
    cudaGetSymbolAddress((void**)&wq16, g_wq16); cudaGetSymbolAddress((void**)&wk16, g_wk16);
    cudaGetSymbolAddress((void**)&wv16, g_wv16); cudaGetSymbolAddress((void**)&wo16, g_wo16);
    cudaGetSymbolAddress((void**)&qh, g_qh); cudaGetSymbolAddress((void**)&ql, g_ql);
    cudaGetSymbolAddress((void**)&kh, g_kh); cudaGetSymbolAddress((void**)&kl, g_kl);
    cudaGetSymbolAddress((void**)&vh, g_vh); cudaGetSymbolAddress((void**)&vl, g_vl);
    cudaGetSymbolAddress((void**)&ah, g_ah); cudaGetSymbolAddress((void**)&al, g_al);

    cudaFuncSetAttribute(gemm_fp16_kernel<false>,
                         cudaFuncAttributeMaxDynamicSharedMemorySize, GEMM_SMEM);
    cudaFuncSetAttribute(gemm_fp16_kernel<true>,
                         cudaFuncAttributeMaxDynamicSharedMemorySize, GEMM_SMEM);
    cudaFuncSetAttribute(qk_gemm_kernel,
                         cudaFuncAttributeMaxDynamicSharedMemorySize, GEMM_SMEM);
    cudaFuncSetAttribute(flash_kernel,
                         cudaFuncAttributeMaxDynamicSharedMemorySize, FLASH_SMEM);

    // 1) splits (launches 1-2)
    const int selem = MROWS * DD;
    dim3 sgrid(selem / 1024, 1, 2);
    split_fused_kernel<<<sgrid, 256>>>(queries, inqh, inql, keys, inkh, inkl);
    dim3 wtb(32, 8), wtg(32, 32, 4);
    splitw_fused_kernel<<<wtg, wtb>>>(Wq, wq16, Wk, wk16, Wv, wv16, Wo, wo16);

    // 2) fused Q+K projections (launch 3; 1024 CTAs)
    dim3 gblk(256);
    dim3 qkgrid(DD / 128, MROWS / 64, 2);
    qk_gemm_kernel<<<qkgrid, gblk, GEMM_SMEM>>>(
        inqh, inql, inkh, inkl, wq16, wk16, bq, bk, qh, ql, kh, kl);

    // 3) V projection from projected K (launch 4; 512 CTAs)
    dim3 ggrid(DD / 128, MROWS / 64);
    gemm_fp16_kernel<false><<<ggrid, gblk, GEMM_SMEM>>>(
        kh, kl, wv16, bv, 1.0f, vh, vl, nullptr);

    // 4) attention (launch 5) — K, V single fp16
    dim3 fgrid(SS / 128, HH, BB);
    flash_kernel<<<fgrid, dim3(256), FLASH_SMEM>>>(qh, ql, kh, vh, ah, al);

    // 5) output projection (launch 6 -> profiled)
    gemm_fp16_kernel<true><<<ggrid, gblk, GEMM_SMEM>>>(
        ah, al, wo16, bo, 1.0f, nullptr, nullptr, out);
}

// round 16
// speedup vs baseline: 1.4774x; 1.0336x over previous
#include <cuda_runtime.h>
#include <cuda_fp16.h>
#include <cstdint>

// Problem constants
#define BB   2
#define SS   2048
#define DD   1024
#define HH   16
#define HDIM 64
#define MROWS (BB*SS)      // 4096
typedef __half fp16;

// ---------------- scratch (no allocations allowed) ----------------
__device__ fp16 g_inqh[MROWS * DD], g_inql[MROWS * DD];
__device__ fp16 g_inkh[MROWS * DD], g_inkl[MROWS * DD];
__device__ fp16 g_wq16[DD * DD];   // W^T [n][k] single fp16
__device__ fp16 g_wk16[DD * DD];
__device__ fp16 g_wv16[DD * DD];
__device__ fp16 g_wo16[DD * DD];
__device__ fp16 g_qh[MROWS * DD], g_ql[MROWS * DD];
__device__ fp16 g_kh[MROWS * DD], g_kl[MROWS * DD];
__device__ fp16 g_vh[MROWS * DD], g_vl[MROWS * DD];
__device__ fp16 g_ah[MROWS * DD], g_al[MROWS * DD];

// ============================================================================
// helpers
// ============================================================================
__device__ __forceinline__ uint32_t smem_u32(const void* p) {
    uint32_t a;
    asm("{ .reg .u64 t; cvta.to.shared.u64 t, %1; cvt.u32.u64 %0, t; }"
        : "=r"(a) : "l"(p));
    return a;
}
__device__ __forceinline__ void ldsm4(uint32_t* r, uint32_t addr) {
    asm volatile("ldmatrix.sync.aligned.m8n8.x4.shared.b16 {%0,%1,%2,%3}, [%4];"
                 : "=r"(r[0]), "=r"(r[1]), "=r"(r[2]), "=r"(r[3]) : "r"(addr));
}
__device__ __forceinline__ void ldsm4t(uint32_t* r, uint32_t addr) {
    asm volatile("ldmatrix.sync.aligned.m8n8.x4.trans.shared.b16 {%0,%1,%2,%3}, [%4];"
                 : "=r"(r[0]), "=r"(r[1]), "=r"(r[2]), "=r"(r[3]) : "r"(addr));
}
// fp16 mma with fp32 accumulate
__device__ __forceinline__ void mma16816(float* c, const uint32_t* a,
                                         uint32_t b0, uint32_t b1) {
    asm volatile(
        "mma.sync.aligned.m16n8k16.row.col.f32.f16.f16.f32 "
        "{%0,%1,%2,%3}, {%4,%5,%6,%7}, {%8,%9}, {%0,%1,%2,%3};"
        : "+f"(c[0]), "+f"(c[1]), "+f"(c[2]), "+f"(c[3])
        : "r"(a[0]), "r"(a[1]), "r"(a[2]), "r"(a[3]), "r"(b0), "r"(b1));
}
__device__ __forceinline__ void splitpack(float x, float y, uint32_t& hi, uint32_t& lo) {
    fp16 hx = __float2half_rn(x), hy = __float2half_rn(y);
    float rx = x - __half2float(hx);
    float ry = y - __half2float(hy);
    fp16 lx = __float2half_rn(rx), ly = __float2half_rn(ry);
    hi = (uint32_t)__half_as_ushort(hx) | ((uint32_t)__half_as_ushort(hy) << 16);
    lo = (uint32_t)__half_as_ushort(lx) | ((uint32_t)__half_as_ushort(ly) << 16);
}

#define CP_ASYNC16(dst, src) \
    asm volatile("cp.async.cg.shared.global [%0], [%1], 16;" \
                 :: "r"(dst), "l"(src) : "memory")
#define CP_COMMIT() asm volatile("cp.async.commit_group;" ::: "memory")
#define CP_WAIT0()  asm volatile("cp.async.wait_group 0;" ::: "memory")
#define CP_WAIT1()  asm volatile("cp.async.wait_group 1;" ::: "memory")
#define CP_WAIT2()  asm volatile("cp.async.wait_group 2;" ::: "memory")

// ============================================================================
// split kernels
// ============================================================================
__global__ void split_fused_kernel(const float* __restrict__ s0, fp16* h0, fp16* l0,
                                   const float* __restrict__ s1, fp16* h1, fp16* l1)
{
    const float* src = blockIdx.z ? s1 : s0;
    fp16* hi = blockIdx.z ? h1 : h0;
    fp16* lo = blockIdx.z ? l1 : l0;
    const int i = (blockIdx.x * 256 + threadIdx.x) * 4;
    float4 v = *(const float4*)(src + i);
    uint32_t a0, b0, a1, b1;
    splitpack(v.x, v.y, a0, b0);
    splitpack(v.z, v.w, a1, b1);
    *(uint2*)(hi + i) = make_uint2(a0, a1);
    *(uint2*)(lo + i) = make_uint2(b0, b1);
}

// W [k][n] fp32 -> Wt [n][k] single fp16, smem tile transpose; z selects matrix
__global__ void splitw_fused_kernel(
    const float* __restrict__ W0, fp16* t0,
    const float* __restrict__ W1, fp16* t1,
    const float* __restrict__ W2, fp16* t2,
    const float* __restrict__ W3, fp16* t3)
{
    const float* W; fp16* th;
    switch (blockIdx.z) {
        case 0: W = W0; th = t0; break;
        case 1: W = W1; th = t1; break;
        case 2: W = W2; th = t2; break;
        default: W = W3; th = t3; break;
    }
    __shared__ float t[32][33];
    const int tx = threadIdx.x, ty = threadIdx.y;
    const int k0 = blockIdx.y * 32, n0 = blockIdx.x * 32;
    #pragma unroll
    for (int i = 0; i < 4; i++)
        t[ty + i * 8][tx] = W[(size_t)(k0 + ty + i * 8) * DD + n0 + tx];
    __syncthreads();
    #pragma unroll
    for (int i = 0; i < 4; i++)
        th[(size_t)(n0 + ty + i * 8) * DD + k0 + tx] =
            __float2half_rn(t[tx][ty + i * 8]);
}

// ============================================================================
// GEMM (unchanged from passing R14/R15): CTA 64x128, A fp16 hi/lo 2-pass,
// B single fp16. 3-stage cp.async with proven sync. stage = 16K.
// ============================================================================
#define GSTG 16384
#define GEMM_SMEM (3 * GSTG)

template<bool F32OUT>
__device__ __forceinline__ void gemm_body(
    const fp16* __restrict__ Ah, const fp16* __restrict__ Al,
    const fp16* __restrict__ B,
    const float* __restrict__ bias, float scale,
    fp16* __restrict__ Ch, fp16* __restrict__ Cl, float* __restrict__ Cf,
    int bm, int bn)
{
    extern __shared__ char smem[];
    const uint32_t sb = smem_u32(smem);
    const int tid = threadIdx.x, wid = tid >> 5, lane = tid & 31;
    const int mw = wid >> 2;
    const int nwq = wid & 3;

    const int lrA = tid >> 2, lcA = tid & 3;
    const fp16* rAh = Ah + (size_t)(bm * 64 + lrA) * DD;
    const fp16* rAl = Al + (size_t)(bm * 64 + lrA) * DD;
    const uint32_t ldstA = (uint32_t)(lrA * 64 + (lcA ^ ((lrA >> 1) & 3)) * 16);
    const int lrB = tid >> 1, lc0B = (tid & 1) * 2;
    const fp16* rB = B + (size_t)(bn * 128 + lrB) * DD;
    const uint32_t xlB = (lrB >> 1) & 3;
    uint32_t ldstB[2];
    #pragma unroll
    for (int j = 0; j < 2; j++)
        ldstB[j] = (uint32_t)(lrB * 64 + ((lc0B + j) ^ xlB) * 16);

    const int lrow = lane & 15, cl = lane >> 4;
    const uint32_t xg = (lrow >> 1) & 3;
    uint32_t offA[2][2], offB[2][2];
    #pragma unroll
    for (int ks = 0; ks < 2; ks++) {
        const uint32_t cc = (uint32_t)(((ks * 2 + cl) ^ xg) * 16);
        #pragma unroll
        for (int mi = 0; mi < 2; mi++)
            offA[mi][ks] = (uint32_t)((mw * 32 + mi * 16 + lrow) * 64) + cc;
        #pragma unroll
        for (int np = 0; np < 2; np++)
            offB[np][ks] = (uint32_t)((nwq * 32 + np * 16 + lrow) * 64) + cc;
    }

    float acc[2][4][4];
    #pragma unroll
    for (int i = 0; i < 2; i++)
        #pragma unroll
        for (int j = 0; j < 4; j++)
            #pragma unroll
            for (int q = 0; q < 4; q++) acc[i][j][q] = 0.f;

    #pragma unroll
    for (int st = 0; st < 2; st++) {
        const uint32_t base = sb + st * GSTG;
        const int ke = st * 32;
        CP_ASYNC16(base + ldstA,        rAh + ke + lcA * 8);
        CP_ASYNC16(base + 4096 + ldstA, rAl + ke + lcA * 8);
        #pragma unroll
        for (int j = 0; j < 2; j++)
            CP_ASYNC16(base + 8192 + ldstB[j], rB + ke + (lc0B + j) * 8);
        CP_COMMIT();
    }

    int stage = 0;
    for (int kc = 0; kc < 32; kc++) {
        if (kc + 2 < 32) {
            const uint32_t base = sb + ((stage + 2) % 3) * GSTG;
            const int ke = (kc + 2) * 32;
            CP_ASYNC16(base + ldstA,        rAh + ke + lcA * 8);
            CP_ASYNC16(base + 4096 + ldstA, rAl + ke + lcA * 8);
            #pragma unroll
            for (int j = 0; j < 2; j++)
                CP_ASYNC16(base + 8192 + ldstB[j], rB + ke + (lc0B + j) * 8);
            CP_COMMIT();
            CP_WAIT2();
        } else if (kc + 1 < 32) {
            CP_WAIT1();
        } else {
            CP_WAIT0();
        }
        __syncthreads();     // PUBLISH

        const uint32_t B0 = sb + stage * GSTG;
        #pragma unroll
        for (int ks = 0; ks < 2; ks++) {
            uint32_t ah[2][4], al[2][4], bb[2][4];
            ldsm4(ah[0], B0 + offA[0][ks]);
            ldsm4(ah[1], B0 + offA[1][ks]);
            ldsm4(al[0], B0 + 4096 + offA[0][ks]);
            ldsm4(al[1], B0 + 4096 + offA[1][ks]);
            ldsm4(bb[0], B0 + 8192 + offB[0][ks]);
            ldsm4(bb[1], B0 + 8192 + offB[1][ks]);
            #pragma unroll
            for (int np = 0; np < 2; np++)
                #pragma unroll
                for (int hf = 0; hf < 2; hf++)
                    #pragma unroll
                    for (int mi = 0; mi < 2; mi++)
                        mma16816(acc[mi][np * 2 + hf], ah[mi],
                                 bb[np][hf], bb[np][hf + 2]);
            #pragma unroll
            for (int np = 0; np < 2; np++)
                #pragma unroll
                for (int hf = 0; hf < 2; hf++)
                    #pragma unroll
                    for (int mi = 0; mi < 2; mi++)
                        mma16816(acc[mi][np * 2 + hf], al[mi],
                                 bb[np][hf], bb[np][hf + 2]);
        }
        __syncthreads();     // WAR
        stage = (stage + 1) % 3;
    }

    const int tg = lane >> 2, tq = lane & 3;
    #pragma unroll
    for (int mi = 0; mi < 2; mi++) {
        const int gr = bm * 64 + mw * 32 + mi * 16 + tg;
        #pragma unroll
        for (int nj = 0; nj < 4; nj++) {
            const int gc = bn * 128 + nwq * 32 + nj * 8 + tq * 2;
            const float b0 = bias[gc], b1 = bias[gc + 1];
            float* c = acc[mi][nj];
            const float v0 = (c[0] + b0) * scale, v1 = (c[1] + b1) * scale;
            const float v2 = (c[2] + b0) * scale, v3 = (c[3] + b1) * scale;
            if (F32OUT) {
                *(float2*)(Cf + (size_t)gr * DD + gc)       = make_float2(v0, v1);
                *(float2*)(Cf + (size_t)(gr + 8) * DD + gc) = make_float2(v2, v3);
            } else {
                uint32_t h, l;
                splitpack(v0, v1, h, l);
                *(uint32_t*)(Ch + (size_t)gr * DD + gc) = h;
                *(uint32_t*)(Cl + (size_t)gr * DD + gc) = l;
                splitpack(v2, v3, h, l);
                *(uint32_t*)(Ch + (size_t)(gr + 8) * DD + gc) = h;
                *(uint32_t*)(Cl + (size_t)(gr + 8) * DD + gc) = l;
            }
        }
    }
}

template<bool F32OUT>
__global__ __launch_bounds__(256, 3)
void gemm_fp16_kernel(const fp16* __restrict__ Ah, const fp16* __restrict__ Al,
                      const fp16* __restrict__ B,
                      const float* __restrict__ bias, float scale,
                      fp16* __restrict__ Ch, fp16* __restrict__ Cl,
                      float* __restrict__ Cf)
{
    gemm_body<F32OUT>(Ah, Al, B, bias, scale, Ch, Cl, Cf,
                      blockIdx.y, blockIdx.x);
}

__global__ __launch_bounds__(256, 3)
void qk_gemm_kernel(
    const fp16* iqh, const fp16* iql, const fp16* ikh, const fp16* ikl,
    const fp16* wq, const fp16* wk,
    const float* bq, const float* bk,
    fp16* qh, fp16* ql, fp16* kh, fp16* kl)
{
    if (blockIdx.z == 0)
        gemm_body<false>(iqh, iql, wq, bq, 0.125f, qh, ql, nullptr,
                         blockIdx.y, blockIdx.x);
    else
        gemm_body<false>(ikh, ikl, wk, bk, 1.0f, kh, kl, nullptr,
                         blockIdx.y, blockIdx.x);
}

// ============================================================================
// flash attention v4: Q SINGLE fp16, K SINGLE fp16 -> QK 1 pass;
// P hi/lo x single-fp16 V -> PV 2 passes. SW128, 2-stage KV.
// smem: Q 16K | stage{K 8K | V 8K} x2 = 48K -> 3 CTAs/SM.
// ============================================================================
#define FKV0 16384
#define FKVSTG 16384
#define FLASH_SMEM 49152

__global__ __launch_bounds__(256, 3)
void flash_kernel(const fp16* __restrict__ Qh,
                  const fp16* __restrict__ Kh, const fp16* __restrict__ Vh,
                  fp16* __restrict__ Oh, fp16* __restrict__ Ol)
{
    extern __shared__ char smem[];
    const uint32_t sb = smem_u32(smem);
    const int tid = threadIdx.x, wid = tid >> 5, lane = tid & 31;
    const int qt = (gridDim.x - 1) - blockIdx.x;
    const int h = blockIdx.y, b = blockIdx.z;
    const size_t hbase = ((size_t)b * SS) * DD + h * HDIM;
    const int nkt = 2 * qt + 2;

    const int qlr = tid >> 1, qc0 = (tid & 1) * 4;
    const int klr = tid >> 2, kc0 = (tid & 3) * 2;
    const fp16* rQh = Qh + hbase + (size_t)(qt * 128 + qlr) * DD;
    const fp16* rKh = Kh + hbase + (size_t)klr * DD;
    const fp16* rVh = Vh + hbase + (size_t)klr * DD;
    const uint32_t qx = qlr & 7, kx = klr & 7;

    #pragma unroll
    for (int j = 0; j < 4; j++) {
        const uint32_t d = (uint32_t)(qlr * 128 + ((qc0 + j) ^ qx) * 16);
        CP_ASYNC16(sb + d, rQh + (qc0 + j) * 8);
    }
    #pragma unroll
    for (int j = 0; j < 2; j++) {
        const uint32_t d = (uint32_t)(klr * 128 + ((kc0 + j) ^ kx) * 16);
        const int eo = (kc0 + j) * 8;
        CP_ASYNC16(sb + FKV0 + d,        rKh + eo);
        CP_ASYNC16(sb + FKV0 + 8192 + d, rVh + eo);
    }
    CP_COMMIT();

    const int lrow = lane & 15, cl = lane >> 4;
    const uint32_t x = lrow & 7;
    const uint32_t rb = (uint32_t)(lrow * 128);
    const uint32_t qwb = (uint32_t)(wid * 2048);

    float oacc[8][4];
    #pragma unroll
    for (int t = 0; t < 8; t++)
        #pragma unroll
        for (int j = 0; j < 4; j++) oacc[t][j] = 0.f;
    float m0 = -1e30f, m1 = -1e30f, l0 = 0.f, l1 = 0.f;

    for (int kt = 0; kt < nkt; kt++) {
        if (kt + 1 < nkt) {
            const uint32_t base = sb + FKV0 + ((kt + 1) & 1) * FKVSTG;
            const size_t ro = (size_t)(kt + 1) * 64 * DD;
            #pragma unroll
            for (int j = 0; j < 2; j++) {
                const uint32_t d = (uint32_t)(klr * 128 + ((kc0 + j) ^ kx) * 16);
                const int eo = (kc0 + j) * 8;
                CP_ASYNC16(base + d,        rKh + ro + eo);
                CP_ASYNC16(base + 8192 + d, rVh + ro + eo);
            }
            CP_COMMIT();
            CP_WAIT1();
        } else {
            CP_WAIT0();
        }
        __syncthreads();

        const uint32_t kvb = sb + FKV0 + (kt & 1) * FKVSTG;

        float s[8][4];
        #pragma unroll
        for (int t = 0; t < 8; t++)
            #pragma unroll
            for (int j = 0; j < 4; j++) s[t][j] = 0.f;

        // S = Q K^T : 1 pass (single-fp16 Q and K, fp32 accumulate)
        #pragma unroll
        for (int ks = 0; ks < 4; ks++) {
            const uint32_t cc = ((uint32_t)(ks * 2 + cl) ^ x) * 16;
            uint32_t qq[4];
            ldsm4(qq, sb + qwb + rb + cc);
            #pragma unroll
            for (int np = 0; np < 4; np++) {
                uint32_t kk[4];
                ldsm4(kk, kvb + (uint32_t)(np * 2048) + rb + cc);
                mma16816(s[np * 2 + 0], qq, kk[0], kk[2]);
                mma16816(s[np * 2 + 1], qq, kk[1], kk[3]);
            }
        }

        if (kt >= 2 * qt) {
            const int off = (kt - 2 * qt) * 64;
            const int r0 = wid * 16 + (lane >> 2);
            const int cb = (lane & 3) * 2;
            #pragma unroll
            for (int t = 0; t < 8; t++)
                #pragma unroll
                for (int j = 0; j < 2; j++) {
                    const int cg = off + t * 8 + cb + j;
                    if (cg > r0)     s[t][j]     = -1e30f;
                    if (cg > r0 + 8) s[t][2 + j] = -1e30f;
                }
        }

        float mx0 = -1e30f, mx1 = -1e30f;
        #pragma unroll
        for (int t = 0; t < 8; t++) {
            mx0 = fmaxf(mx0, fmaxf(s[t][0], s[t][1]));
            mx1 = fmaxf(mx1, fmaxf(s[t][2], s[t][3]));
        }
        mx0 = fmaxf(mx0, __shfl_xor_sync(0xffffffffu, mx0, 1));
        mx0 = fmaxf(mx0, __shfl_xor_sync(0xffffffffu, mx0, 2));
        mx1 = fmaxf(mx1, __shfl_xor_sync(0xffffffffu, mx1, 1));
        mx1 = fmaxf(mx1, __shfl_xor_sync(0xffffffffu, mx1, 2));

        const float mn0 = fmaxf(m0, mx0);
        const float mn1 = fmaxf(m1, mx1);
        const float al0 = __expf(m0 - mn0);
        const float al1 = __expf(m1 - mn1);
        m0 = mn0; m1 = mn1;

        float ls0 = 0.f, ls1 = 0.f;
        #pragma unroll
        for (int t = 0; t < 8; t++) {
            s[t][0] = __expf(s[t][0] - mn0); ls0 += s[t][0];
            s[t][1] = __expf(s[t][1] - mn0); ls0 += s[t][1];
            s[t][2] = __expf(s[t][2] - mn1); ls1 += s[t][2];
            s[t][3] = __expf(s[t][3] - mn1); ls1 += s[t][3];
        }
        ls0 += __shfl_xor_sync(0xffffffffu, ls0, 1);
        ls0 += __shfl_xor_sync(0xffffffffu, ls0, 2);
        ls1 += __shfl_xor_sync(0xffffffffu, ls1, 1);
        ls1 += __shfl_xor_sync(0xffffffffu, ls1, 2);
        l0 = l0 * al0 + ls0;
        l1 = l1 * al1 + ls1;
        #pragma unroll
        for (int t = 0; t < 8; t++) {
            oacc[t][0] *= al0; oacc[t][1] *= al0;
            oacc[t][2] *= al1; oacc[t][3] *= al1;
        }

        // O += P V : 2 passes (phi + plo) over single-fp16 V
        #pragma unroll
        for (int t = 0; t < 4; t++) {
            uint32_t aPhi[4], aPlo[4];
            splitpack(s[2 * t][0],     s[2 * t][1],     aPhi[0], aPlo[0]);
            splitpack(s[2 * t][2],     s[2 * t][3],     aPhi[1], aPlo[1]);
            splitpack(s[2 * t + 1][0], s[2 * t + 1][1], aPhi[2], aPlo[2]);
            splitpack(s[2 * t + 1][2], s[2 * t + 1][3], aPhi[3], aPlo[3]);
            #pragma unroll
            for (int np = 0; np < 4; np++) {
                const uint32_t cc = ((uint32_t)(np * 2 + cl) ^ x) * 16;
                uint32_t vv[4];
                ldsm4t(vv, kvb + 8192 + (uint32_t)(t * 2048) + rb + cc);
                float* o0 = oacc[np * 2 + 0];
                float* o1 = oacc[np * 2 + 1];
                mma16816(o0, aPhi, vv[0], vv[1]);
                mma16816(o1, aPhi, vv[2], vv[3]);
                mma16816(o0, aPlo, vv[0], vv[1]);
                mma16816(o1, aPlo, vv[2], vv[3]);
            }
        }
        __syncthreads();
    }

    const float inv0 = 1.0f / l0;
    const float inv1 = 1.0f / l1;
    const int r0 = qt * 128 + wid * 16 + (lane >> 2);
    const int cb = (lane & 3) * 2;
    #pragma unroll
    for (int t = 0; t < 8; t++) {
        uint32_t h0, lo0, h1, lo1;
        splitpack(oacc[t][0] * inv0, oacc[t][1] * inv0, h0, lo0);
        splitpack(oacc[t][2] * inv1, oacc[t][3] * inv1, h1, lo1);
        const size_t o0 = hbase + (size_t)r0 * DD + t * 8 + cb;
        const size_t o1 = hbase + (size_t)(r0 + 8) * DD + t * 8 + cb;
        *(uint32_t*)(Oh + o0) = h0;
        *(uint32_t*)(Ol + o0) = lo0;
        *(uint32_t*)(Oh + o1) = h1;
        *(uint32_t*)(Ol + o1) = lo1;
    }
}

// ---------------- launch ----------------
extern "C" void kernel_launch(void* const* d_in, const int* in_sizes, int n_in,
                              void* d_out, int out_size)
{
    const float* queries = (const float*)d_in[0];
    const float* keys    = (const float*)d_in[1];
    const float* Wq = (const float*)d_in[4];
    const float* bq = (const float*)d_in[5];
    const float* Wk = (const float*)d_in[6];
    const float* bk = (const float*)d_in[7];
    const float* Wv = (const float*)d_in[8];
    const float* bv = (const float*)d_in[9];
    const float* Wo = (const float*)d_in[10];
    const float* bo = (const float*)d_in[11];
    float* out = (float*)d_out;

    fp16 *inqh, *inql, *inkh, *inkl;
    fp16 *wq16, *wk16, *wv16, *wo16;
    fp16 *qh, *ql, *kh, *kl, *vh, *vl, *ah, *al;
    cudaGetSymbolAddress((void**)&inqh, g_inqh); cudaGetSymbolAddress((void**)&inql, g_inql);
    cudaGetSymbolAddress((void**)&inkh, g_inkh); cudaGetSymbolAddress((void**)&inkl, g_inkl);
    cudaGetSymbolAddress((void**)&wq16, g_wq16); cudaGetSymbolAddress((void**)&wk16, g_wk16);
    cudaGetSymbolAddress((void**)&wv16, g_wv16); cudaGetSymbolAddress((void**)&wo16, g_wo16);
    cudaGetSymbolAddress((void**)&qh, g_qh); cudaGetSymbolAddress((void**)&ql, g_ql);
    cudaGetSymbolAddress((void**)&kh, g_kh); cudaGetSymbolAddress((void**)&kl, g_kl);
    cudaGetSymbolAddress((void**)&vh, g_vh); cudaGetSymbolAddress((void**)&vl, g_vl);
    cudaGetSymbolAddress((void**)&ah, g_ah); cudaGetSymbolAddress((void**)&al, g_al);

    cudaFuncSetAttribute(gemm_fp16_kernel<false>,
                         cudaFuncAttributeMaxDynamicSharedMemorySize, GEMM_SMEM);
    cudaFuncSetAttribute(gemm_fp16_kernel<true>,
                         cudaFuncAttributeMaxDynamicSharedMemorySize, GEMM_SMEM);
    cudaFuncSetAttribute(qk_gemm_kernel,
                         cudaFuncAttributeMaxDynamicSharedMemorySize, GEMM_SMEM);
    cudaFuncSetAttribute(flash_kernel,
                         cudaFuncAttributeMaxDynamicSharedMemorySize, FLASH_SMEM);

    // 1) splits (launches 1-2)
    const int selem = MROWS * DD;
    dim3 sgrid(selem / 1024, 1, 2);
    split_fused_kernel<<<sgrid, 256>>>(queries, inqh, inql, keys, inkh, inkl);
    dim3 wtb(32, 8), wtg(32, 32, 4);
    splitw_fused_kernel<<<wtg, wtb>>>(Wq, wq16, Wk, wk16, Wv, wv16, Wo, wo16);

    // 2) fused Q+K projections (launch 3; 1024 CTAs)
    dim3 gblk(256);
    dim3 qkgrid(DD / 128, MROWS / 64, 2);
    qk_gemm_kernel<<<qkgrid, gblk, GEMM_SMEM>>>(
        inqh, inql, inkh, inkl, wq16, wk16, bq, bk, qh, ql, kh, kl);

    // 3) V projection from projected K (launch 4; 512 CTAs)
    dim3 ggrid(DD / 128, MROWS / 64);
    gemm_fp16_kernel<false><<<ggrid, gblk, GEMM_SMEM>>>(
        kh, kl, wv16, bv, 1.0f, vh, vl, nullptr);

    // 4) attention (launch 5) — Q, K, V single fp16 operands
    dim3 fgrid(SS / 128, HH, BB);
    flash_kernel<<<fgrid, dim3(256), FLASH_SMEM>>>(qh, kh, vh, ah, al);

    // 5) output projection (launch 6 -> profiled)
    gemm_fp16_kernel<true><<<ggrid, gblk, GEMM_SMEM>>>(
        ah, al, wo16, bo, 1.0f, nullptr, nullptr, out);
}

// round 17
// speedup vs baseline: 1.7153x; 1.1610x over previous
#include <cuda_runtime.h>
#include <cuda_fp16.h>
#include <cstdint>

// Problem constants
#define BB   2
#define SS   2048
#define DD   1024
#define HH   16
#define HDIM 64
#define MROWS (BB*SS)      // 4096
typedef __half fp16;

// ---------------- scratch (no allocations allowed) ----------------
__device__ fp16 g_inqh[MROWS * DD], g_inql[MROWS * DD];
__device__ fp16 g_inkh[MROWS * DD], g_inkl[MROWS * DD];
__device__ fp16 g_wq16[DD * DD];   // W^T [n][k] single fp16
__device__ fp16 g_wk16[DD * DD];
__device__ fp16 g_wv16[DD * DD];
__device__ fp16 g_wo16[DD * DD];
__device__ fp16 g_qh[MROWS * DD], g_ql[MROWS * DD];
__device__ fp16 g_kh[MROWS * DD], g_kl[MROWS * DD];
__device__ fp16 g_vh[MROWS * DD], g_vl[MROWS * DD];
__device__ fp16 g_ah[MROWS * DD];

// ============================================================================
// helpers
// ============================================================================
__device__ __forceinline__ uint32_t smem_u32(const void* p) {
    uint32_t a;
    asm("{ .reg .u64 t; cvta.to.shared.u64 t, %1; cvt.u32.u64 %0, t; }"
        : "=r"(a) : "l"(p));
    return a;
}
__device__ __forceinline__ void ldsm4(uint32_t* r, uint32_t addr) {
    asm volatile("ldmatrix.sync.aligned.m8n8.x4.shared.b16 {%0,%1,%2,%3}, [%4];"
                 : "=r"(r[0]), "=r"(r[1]), "=r"(r[2]), "=r"(r[3]) : "r"(addr));
}
__device__ __forceinline__ void ldsm4t(uint32_t* r, uint32_t addr) {
    asm volatile("ldmatrix.sync.aligned.m8n8.x4.trans.shared.b16 {%0,%1,%2,%3}, [%4];"
                 : "=r"(r[0]), "=r"(r[1]), "=r"(r[2]), "=r"(r[3]) : "r"(addr));
}
// fp16 mma with fp32 accumulate
__device__ __forceinline__ void mma16816(float* c, const uint32_t* a,
                                         uint32_t b0, uint32_t b1) {
    asm volatile(
        "mma.sync.aligned.m16n8k16.row.col.f32.f16.f16.f32 "
        "{%0,%1,%2,%3}, {%4,%5,%6,%7}, {%8,%9}, {%0,%1,%2,%3};"
        : "+f"(c[0]), "+f"(c[1]), "+f"(c[2]), "+f"(c[3])
        : "r"(a[0]), "r"(a[1]), "r"(a[2]), "r"(a[3]), "r"(b0), "r"(b1));
}
__device__ __forceinline__ void splitpack(float x, float y, uint32_t& hi, uint32_t& lo) {
    fp16 hx = __float2half_rn(x), hy = __float2half_rn(y);
    float rx = x - __half2float(hx);
    float ry = y - __half2float(hy);
    fp16 lx = __float2half_rn(rx), ly = __float2half_rn(ry);
    hi = (uint32_t)__half_as_ushort(hx) | ((uint32_t)__half_as_ushort(hy) << 16);
    lo = (uint32_t)__half_as_ushort(lx) | ((uint32_t)__half_as_ushort(ly) << 16);
}
__device__ __forceinline__ uint32_t pack2(float x, float y) {
    fp16 hx = __float2half_rn(x), hy = __float2half_rn(y);
    return (uint32_t)__half_as_ushort(hx) | ((uint32_t)__half_as_ushort(hy) << 16);
}

#define CP_ASYNC16(dst, src) \
    asm volatile("cp.async.cg.shared.global [%0], [%1], 16;" \
                 :: "r"(dst), "l"(src) : "memory")
#define CP_COMMIT() asm volatile("cp.async.commit_group;" ::: "memory")
#define CP_WAIT0()  asm volatile("cp.async.wait_group 0;" ::: "memory")
#define CP_WAIT1()  asm volatile("cp.async.wait_group 1;" ::: "memory")
#define CP_WAIT2()  asm volatile("cp.async.wait_group 2;" ::: "memory")

// ============================================================================
// split kernels
// ============================================================================
__global__ void split_fused_kernel(const float* __restrict__ s0, fp16* h0, fp16* l0,
                                   const float* __restrict__ s1, fp16* h1, fp16* l1)
{
    const float* src = blockIdx.z ? s1 : s0;
    fp16* hi = blockIdx.z ? h1 : h0;
    fp16* lo = blockIdx.z ? l1 : l0;
    const int i = (blockIdx.x * 256 + threadIdx.x) * 4;
    float4 v = *(const float4*)(src + i);
    uint32_t a0, b0, a1, b1;
    splitpack(v.x, v.y, a0, b0);
    splitpack(v.z, v.w, a1, b1);
    *(uint2*)(hi + i) = make_uint2(a0, a1);
    *(uint2*)(lo + i) = make_uint2(b0, b1);
}

// W [k][n] fp32 -> Wt [n][k] single fp16, smem tile transpose; z selects matrix
__global__ void splitw_fused_kernel(
    const float* __restrict__ W0, fp16* t0,
    const float* __restrict__ W1, fp16* t1,
    const float* __restrict__ W2, fp16* t2,
    const float* __restrict__ W3, fp16* t3)
{
    const float* W; fp16* th;
    switch (blockIdx.z) {
        case 0: W = W0; th = t0; break;
        case 1: W = W1; th = t1; break;
        case 2: W = W2; th = t2; break;
        default: W = W3; th = t3; break;
    }
    __shared__ float t[32][33];
    const int tx = threadIdx.x, ty = threadIdx.y;
    const int k0 = blockIdx.y * 32, n0 = blockIdx.x * 32;
    #pragma unroll
    for (int i = 0; i < 4; i++)
        t[ty + i * 8][tx] = W[(size_t)(k0 + ty + i * 8) * DD + n0 + tx];
    __syncthreads();
    #pragma unroll
    for (int i = 0; i < 4; i++)
        th[(size_t)(n0 + ty + i * 8) * DD + k0 + tx] =
            __float2half_rn(t[tx][ty + i * 8]);
}

// ============================================================================
// GEMM: CTA 64x128. Template ALO: true = A hi/lo 2-pass (unchanged R16 path),
// false = A single fp16 1-pass. B single fp16. 3-stage cp.async, proven sync.
// stage: ALO ? (A 4K|Alo 4K|B 8K = 16K) : (A 4K|B 8K = 12K)
// ============================================================================
#define GSTG2 16384
#define GSTG1 12288
#define GEMM_SMEM2 (3 * GSTG2)
#define GEMM_SMEM1 (3 * GSTG1)

template<bool F32OUT, bool ALO>
__device__ __forceinline__ void gemm_body(
    const fp16* __restrict__ Ah, const fp16* __restrict__ Al,
    const fp16* __restrict__ B,
    const float* __restrict__ bias, float scale,
    fp16* __restrict__ Ch, fp16* __restrict__ Cl, float* __restrict__ Cf,
    int bm, int bn)
{
    constexpr uint32_t STG  = ALO ? GSTG2 : GSTG1;
    constexpr uint32_t BOFF = ALO ? 8192 : 4096;

    extern __shared__ char smem[];
    const uint32_t sb = smem_u32(smem);
    const int tid = threadIdx.x, wid = tid >> 5, lane = tid & 31;
    const int mw = wid >> 2;
    const int nwq = wid & 3;

    const int lrA = tid >> 2, lcA = tid & 3;
    const fp16* rAh = Ah + (size_t)(bm * 64 + lrA) * DD;
    const fp16* rAl = ALO ? Al + (size_t)(bm * 64 + lrA) * DD : nullptr;
    const uint32_t ldstA = (uint32_t)(lrA * 64 + (lcA ^ ((lrA >> 1) & 3)) * 16);
    const int lrB = tid >> 1, lc0B = (tid & 1) * 2;
    const fp16* rB = B + (size_t)(bn * 128 + lrB) * DD;
    const uint32_t xlB = (lrB >> 1) & 3;
    uint32_t ldstB[2];
    #pragma unroll
    for (int j = 0; j < 2; j++)
        ldstB[j] = (uint32_t)(lrB * 64 + ((lc0B + j) ^ xlB) * 16);

    const int lrow = lane & 15, cl = lane >> 4;
    const uint32_t xg = (lrow >> 1) & 3;
    uint32_t offA[2][2], offB[2][2];
    #pragma unroll
    for (int ks = 0; ks < 2; ks++) {
        const uint32_t cc = (uint32_t)(((ks * 2 + cl) ^ xg) * 16);
        #pragma unroll
        for (int mi = 0; mi < 2; mi++)
            offA[mi][ks] = (uint32_t)((mw * 32 + mi * 16 + lrow) * 64) + cc;
        #pragma unroll
        for (int np = 0; np < 2; np++)
            offB[np][ks] = (uint32_t)((nwq * 32 + np * 16 + lrow) * 64) + cc;
    }

    float acc[2][4][4];
    #pragma unroll
    for (int i = 0; i < 2; i++)
        #pragma unroll
        for (int j = 0; j < 4; j++)
            #pragma unroll
            for (int q = 0; q < 4; q++) acc[i][j][q] = 0.f;

    #pragma unroll
    for (int st = 0; st < 2; st++) {
        const uint32_t base = sb + st * STG;
        const int ke = st * 32;
        CP_ASYNC16(base + ldstA, rAh + ke + lcA * 8);
        if (ALO) CP_ASYNC16(base + 4096 + ldstA, rAl + ke + lcA * 8);
        #pragma unroll
        for (int j = 0; j < 2; j++)
            CP_ASYNC16(base + BOFF + ldstB[j], rB + ke + (lc0B + j) * 8);
        CP_COMMIT();
    }

    int stage = 0;
    for (int kc = 0; kc < 32; kc++) {
        if (kc + 2 < 32) {
            const uint32_t base = sb + ((stage + 2) % 3) * STG;
            const int ke = (kc + 2) * 32;
            CP_ASYNC16(base + ldstA, rAh + ke + lcA * 8);
            if (ALO) CP_ASYNC16(base + 4096 + ldstA, rAl + ke + lcA * 8);
            #pragma unroll
            for (int j = 0; j < 2; j++)
                CP_ASYNC16(base + BOFF + ldstB[j], rB + ke + (lc0B + j) * 8);
            CP_COMMIT();
            CP_WAIT2();
        } else if (kc + 1 < 32) {
            CP_WAIT1();
        } else {
            CP_WAIT0();
        }
        __syncthreads();     // PUBLISH

        const uint32_t B0 = sb + stage * STG;
        #pragma unroll
        for (int ks = 0; ks < 2; ks++) {
            uint32_t ah[2][4], al[2][4], bb[2][4];
            ldsm4(ah[0], B0 + offA[0][ks]);
            ldsm4(ah[1], B0 + offA[1][ks]);
            if (ALO) {
                ldsm4(al[0], B0 + 4096 + offA[0][ks]);
                ldsm4(al[1], B0 + 4096 + offA[1][ks]);
            }
            ldsm4(bb[0], B0 + BOFF + offB[0][ks]);
            ldsm4(bb[1], B0 + BOFF + offB[1][ks]);
            #pragma unroll
            for (int np = 0; np < 2; np++)
                #pragma unroll
                for (int hf = 0; hf < 2; hf++)
                    #pragma unroll
                    for (int mi = 0; mi < 2; mi++)
                        mma16816(acc[mi][np * 2 + hf], ah[mi],
                                 bb[np][hf], bb[np][hf + 2]);
            if (ALO) {
                #pragma unroll
                for (int np = 0; np < 2; np++)
                    #pragma unroll
                    for (int hf = 0; hf < 2; hf++)
                        #pragma unroll
                        for (int mi = 0; mi < 2; mi++)
                            mma16816(acc[mi][np * 2 + hf], al[mi],
                                     bb[np][hf], bb[np][hf + 2]);
            }
        }
        __syncthreads();     // WAR
        stage = (stage + 1) % 3;
    }

    const int tg = lane >> 2, tq = lane & 3;
    #pragma unroll
    for (int mi = 0; mi < 2; mi++) {
        const int gr = bm * 64 + mw * 32 + mi * 16 + tg;
        #pragma unroll
        for (int nj = 0; nj < 4; nj++) {
            const int gc = bn * 128 + nwq * 32 + nj * 8 + tq * 2;
            const float b0 = bias[gc], b1 = bias[gc + 1];
            float* c = acc[mi][nj];
            const float v0 = (c[0] + b0) * scale, v1 = (c[1] + b1) * scale;
            const float v2 = (c[2] + b0) * scale, v3 = (c[3] + b1) * scale;
            if (F32OUT) {
                *(float2*)(Cf + (size_t)gr * DD + gc)       = make_float2(v0, v1);
                *(float2*)(Cf + (size_t)(gr + 8) * DD + gc) = make_float2(v2, v3);
            } else {
                uint32_t h, l;
                splitpack(v0, v1, h, l);
                *(uint32_t*)(Ch + (size_t)gr * DD + gc) = h;
                *(uint32_t*)(Cl + (size_t)gr * DD + gc) = l;
                splitpack(v2, v3, h, l);
                *(uint32_t*)(Ch + (size_t)(gr + 8) * DD + gc) = h;
                *(uint32_t*)(Cl + (size_t)(gr + 8) * DD + gc) = l;
            }
        }
    }
}

template<bool F32OUT, bool ALO>
__global__ __launch_bounds__(256, 3)
void gemm_fp16_kernel(const fp16* __restrict__ Ah, const fp16* __restrict__ Al,
                      const fp16* __restrict__ B,
                      const float* __restrict__ bias, float scale,
                      fp16* __restrict__ Ch, fp16* __restrict__ Cl,
                      float* __restrict__ Cf)
{
    gemm_body<F32OUT, ALO>(Ah, Al, B, bias, scale, Ch, Cl, Cf,
                           blockIdx.y, blockIdx.x);
}

__global__ __launch_bounds__(256, 3)
void qk_gemm_kernel(
    const fp16* iqh, const fp16* iql, const fp16* ikh, const fp16* ikl,
    const fp16* wq, const fp16* wk,
    const float* bq, const float* bk,
    fp16* qh, fp16* ql, fp16* kh, fp16* kl)
{
    if (blockIdx.z == 0)
        gemm_body<false, true>(iqh, iql, wq, bq, 0.125f, qh, ql, nullptr,
                               blockIdx.y, blockIdx.x);
    else
        gemm_body<false, true>(ikh, ikl, wk, bk, 1.0f, kh, kl, nullptr,
                               blockIdx.y, blockIdx.x);
}

// ============================================================================
// flash attention v5: Q, K, V, P all single fp16 (fp32 accumulate throughout);
// QK 1 pass, PV 1 pass. Output single fp16. SW128, 2-stage KV.
// smem: Q 16K | stage{K 8K | V 8K} x2 = 48K -> 3 CTAs/SM.
// ============================================================================
#define FKV0 16384
#define FKVSTG 16384
#define FLASH_SMEM 49152

__global__ __launch_bounds__(256, 3)
void flash_kernel(const fp16* __restrict__ Qh,
                  const fp16* __restrict__ Kh, const fp16* __restrict__ Vh,
                  fp16* __restrict__ Oh)
{
    extern __shared__ char smem[];
    const uint32_t sb = smem_u32(smem);
    const int tid = threadIdx.x, wid = tid >> 5, lane = tid & 31;
    const int qt = (gridDim.x - 1) - blockIdx.x;
    const int h = blockIdx.y, b = blockIdx.z;
    const size_t hbase = ((size_t)b * SS) * DD + h * HDIM;
    const int nkt = 2 * qt + 2;

    const int qlr = tid >> 1, qc0 = (tid & 1) * 4;
    const int klr = tid >> 2, kc0 = (tid & 3) * 2;
    const fp16* rQh = Qh + hbase + (size_t)(qt * 128 + qlr) * DD;
    const fp16* rKh = Kh + hbase + (size_t)klr * DD;
    const fp16* rVh = Vh + hbase + (size_t)klr * DD;
    const uint32_t qx = qlr & 7, kx = klr & 7;

    #pragma unroll
    for (int j = 0; j < 4; j++) {
        const uint32_t d = (uint32_t)(qlr * 128 + ((qc0 + j) ^ qx) * 16);
        CP_ASYNC16(sb + d, rQh + (qc0 + j) * 8);
    }
    #pragma unroll
    for (int j = 0; j < 2; j++) {
        const uint32_t d = (uint32_t)(klr * 128 + ((kc0 + j) ^ kx) * 16);
        const int eo = (kc0 + j) * 8;
        CP_ASYNC16(sb + FKV0 + d,        rKh + eo);
        CP_ASYNC16(sb + FKV0 + 8192 + d, rVh + eo);
    }
    CP_COMMIT();

    const int lrow = lane & 15, cl = lane >> 4;
    const uint32_t x = lrow & 7;
    const uint32_t rb = (uint32_t)(lrow * 128);
    const uint32_t qwb = (uint32_t)(wid * 2048);

    float oacc[8][4];
    #pragma unroll
    for (int t = 0; t < 8; t++)
        #pragma unroll
        for (int j = 0; j < 4; j++) oacc[t][j] = 0.f;
    float m0 = -1e30f, m1 = -1e30f, l0 = 0.f, l1 = 0.f;

    for (int kt = 0; kt < nkt; kt++) {
        if (kt + 1 < nkt) {
            const uint32_t base = sb + FKV0 + ((kt + 1) & 1) * FKVSTG;
            const size_t ro = (size_t)(kt + 1) * 64 * DD;
            #pragma unroll
            for (int j = 0; j < 2; j++) {
                const uint32_t d = (uint32_t)(klr * 128 + ((kc0 + j) ^ kx) * 16);
                const int eo = (kc0 + j) * 8;
                CP_ASYNC16(base + d,        rKh + ro + eo);
                CP_ASYNC16(base + 8192 + d, rVh + ro + eo);
            }
            CP_COMMIT();
            CP_WAIT1();
        } else {
            CP_WAIT0();
        }
        __syncthreads();

        const uint32_t kvb = sb + FKV0 + (kt & 1) * FKVSTG;

        float s[8][4];
        #pragma unroll
        for (int t = 0; t < 8; t++)
            #pragma unroll
            for (int j = 0; j < 4; j++) s[t][j] = 0.f;

        // S = Q K^T : 1 pass
        #pragma unroll
        for (int ks = 0; ks < 4; ks++) {
            const uint32_t cc = ((uint32_t)(ks * 2 + cl) ^ x) * 16;
            uint32_t qq[4];
            ldsm4(qq, sb + qwb + rb + cc);
            #pragma unroll
            for (int np = 0; np < 4; np++) {
                uint32_t kk[4];
                ldsm4(kk, kvb + (uint32_t)(np * 2048) + rb + cc);
                mma16816(s[np * 2 + 0], qq, kk[0], kk[2]);
                mma16816(s[np * 2 + 1], qq, kk[1], kk[3]);
            }
        }

        if (kt >= 2 * qt) {
            const int off = (kt - 2 * qt) * 64;
            const int r0 = wid * 16 + (lane >> 2);
            const int cb = (lane & 3) * 2;
            #pragma unroll
            for (int t = 0; t < 8; t++)
                #pragma unroll
                for (int j = 0; j < 2; j++) {
                    const int cg = off + t * 8 + cb + j;
                    if (cg > r0)     s[t][j]     = -1e30f;
                    if (cg > r0 + 8) s[t][2 + j] = -1e30f;
                }
        }

        float mx0 = -1e30f, mx1 = -1e30f;
        #pragma unroll
        for (int t = 0; t < 8; t++) {
            mx0 = fmaxf(mx0, fmaxf(s[t][0], s[t][1]));
            mx1 = fmaxf(mx1, fmaxf(s[t][2], s[t][3]));
        }
        mx0 = fmaxf(mx0, __shfl_xor_sync(0xffffffffu, mx0, 1));
        mx0 = fmaxf(mx0, __shfl_xor_sync(0xffffffffu, mx0, 2));
        mx1 = fmaxf(mx1, __shfl_xor_sync(0xffffffffu, mx1, 1));
        mx1 = fmaxf(mx1, __shfl_xor_sync(0xffffffffu, mx1, 2));

        const float mn0 = fmaxf(m0, mx0);
        const float mn1 = fmaxf(m1, mx1);
        const float al0 = __expf(m0 - mn0);
        const float al1 = __expf(m1 - mn1);
        m0 = mn0; m1 = mn1;

        float ls0 = 0.f, ls1 = 0.f;
        #pragma unroll
        for (int t = 0; t < 8; t++) {
            s[t][0] = __expf(s[t][0] - mn0); ls0 += s[t][0];
            s[t][1] = __expf(s[t][1] - mn0); ls0 += s[t][1];
            s[t][2] = __expf(s[t][2] - mn1); ls1 += s[t][2];
            s[t][3] = __expf(s[t][3] - mn1); ls1 += s[t][3];
        }
        ls0 += __shfl_xor_sync(0xffffffffu, ls0, 1);
        ls0 += __shfl_xor_sync(0xffffffffu, ls0, 2);
        ls1 += __shfl_xor_sync(0xffffffffu, ls1, 1);
        ls1 += __shfl_xor_sync(0xffffffffu, ls1, 2);
        l0 = l0 * al0 + ls0;
        l1 = l1 * al1 + ls1;
        #pragma unroll
        for (int t = 0; t < 8; t++) {
            oacc[t][0] *= al0; oacc[t][1] *= al0;
            oacc[t][2] *= al1; oacc[t][3] *= al1;
        }

        // O += P V : 1 pass (single-fp16 P and V)
        #pragma unroll
        for (int t = 0; t < 4; t++) {
            uint32_t aP[4];
            aP[0] = pack2(s[2 * t][0],     s[2 * t][1]);
            aP[1] = pack2(s[2 * t][2],     s[2 * t][3]);
            aP[2] = pack2(s[2 * t + 1][0], s[2 * t + 1][1]);
            aP[3] = pack2(s[2 * t + 1][2], s[2 * t + 1][3]);
            #pragma unroll
            for (int np = 0; np < 4; np++) {
                const uint32_t cc = ((uint32_t)(np * 2 + cl) ^ x) * 16;
                uint32_t vv[4];
                ldsm4t(vv, kvb + 8192 + (uint32_t)(t * 2048) + rb + cc);
                mma16816(oacc[np * 2 + 0], aP, vv[0], vv[1]);
                mma16816(oacc[np * 2 + 1], aP, vv[2], vv[3]);
            }
        }
        __syncthreads();
    }

    const float inv0 = 1.0f / l0;
    const float inv1 = 1.0f / l1;
    const int r0 = qt * 128 + wid * 16 + (lane >> 2);
    const int cb = (lane & 3) * 2;
    #pragma unroll
    for (int t = 0; t < 8; t++) {
        const size_t o0 = hbase + (size_t)r0 * DD + t * 8 + cb;
        const size_t o1 = hbase + (size_t)(r0 + 8) * DD + t * 8 + cb;
        *(uint32_t*)(Oh + o0) = pack2(oacc[t][0] * inv0, oacc[t][1] * inv0);
        *(uint32_t*)(Oh + o1) = pack2(oacc[t][2] * inv1, oacc[t][3] * inv1);
    }
}

// ---------------- launch ----------------
extern "C" void kernel_launch(void* const* d_in, const int* in_sizes, int n_in,
                              void* d_out, int out_size)
{
    const float* queries = (const float*)d_in[0];
    const float* keys    = (const float*)d_in[1];
    const float* Wq = (const float*)d_in[4];
    const float* bq = (const float*)d_in[5];
    const float* Wk = (const float*)d_in[6];
    const float* bk = (const float*)d_in[7];
    const float* Wv = (const float*)d_in[8];
    const float* bv = (const float*)d_in[9];
    const float* Wo = (const float*)d_in[10];
    const float* bo = (const float*)d_in[11];
    float* out = (float*)d_out;

    fp16 *inqh, *inql, *inkh, *inkl;
    fp16 *wq16, *wk16, *wv16, *wo16;
    fp16 *qh, *ql, *kh, *kl, *vh, *vl, *ah;
    cudaGetSymbolAddress((void**)&inqh, g_inqh); cudaGetSymbolAddress((void**)&inql, g_inql);
    cudaGetSymbolAddress((void**)&inkh, g_inkh); cudaGetSymbolAddress((void**)&inkl, g_inkl);
    cudaGetSymbolAddress((void**)&wq16, g_wq16); cudaGetSymbolAddress((void**)&wk16, g_wk16);
    cudaGetSymbolAddress((void**)&wv16, g_wv16); cudaGetSymbolAddress((void**)&wo16, g_wo16);
    cudaGetSymbolAddress((void**)&qh, g_qh); cudaGetSymbolAddress((void**)&ql, g_ql);
    cudaGetSymbolAddress((void**)&kh, g_kh); cudaGetSymbolAddress((void**)&kl, g_kl);
    cudaGetSymbolAddress((void**)&vh, g_vh); cudaGetSymbolAddress((void**)&vl, g_vl);
    cudaGetSymbolAddress((void**)&ah, g_ah);

    cudaFuncSetAttribute((const void*)gemm_fp16_kernel<false, true>,
                         cudaFuncAttributeMaxDynamicSharedMemorySize, GEMM_SMEM2);
    cudaFuncSetAttribute((const void*)gemm_fp16_kernel<true, false>,
                         cudaFuncAttributeMaxDynamicSharedMemorySize, GEMM_SMEM1);
    cudaFuncSetAttribute((const void*)qk_gemm_kernel,
                         cudaFuncAttributeMaxDynamicSharedMemorySize, GEMM_SMEM2);
    cudaFuncSetAttribute((const void*)flash_kernel,
                         cudaFuncAttributeMaxDynamicSharedMemorySize, FLASH_SMEM);

    // 1) splits (launches 1-2)
    const int selem = MROWS * DD;
    dim3 sgrid(selem / 1024, 1, 2);
    split_fused_kernel<<<sgrid, 256>>>(queries, inqh, inql, keys, inkh, inkl);
    dim3 wtb(32, 8), wtg(32, 32, 4);
    splitw_fused_kernel<<<wtg, wtb>>>(Wq, wq16, Wk, wk16, Wv, wv16, Wo, wo16);

    // 2) fused Q+K projections (launch 3; 1024 CTAs)
    dim3 gblk(256);
    dim3 qkgrid(DD / 128, MROWS / 64, 2);
    qk_gemm_kernel<<<qkgrid, gblk, GEMM_SMEM2>>>(
        inqh, inql, inkh, inkl, wq16, wk16, bq, bk, qh, ql, kh, kl);

    // 3) V projection from projected K (launch 4; 512 CTAs)
    dim3 ggrid(DD / 128, MROWS / 64);
    gemm_fp16_kernel<false, true><<<ggrid, gblk, GEMM_SMEM2>>>(
        kh, kl, wv16, bv, 1.0f, vh, vl, nullptr);

    // 4) attention (launch 5) — all single fp16 operands, fp32 accum
    dim3 fgrid(SS / 128, HH, BB);
    flash_kernel<<<fgrid, dim3(256), FLASH_SMEM>>>(qh, kh, vh, ah);

    // 5) output projection (launch 6) — 1-pass A, fp32 out
    gemm_fp16_kernel<true, false><<<ggrid, gblk, GEMM_SMEM1>>>(
        ah, nullptr, wo16, bo, 1.0f, nullptr, nullptr, out);
}